// round 1
// baseline (speedup 1.0000x reference)
#include <cuda_runtime.h>
#include <cstdint>

// HGCN collapses (see analysis) to:
//   t0 = ztc(x @ W_embed)
//   a0 = ztc(relu(adj @ (t0@W0+b0) / 100))
//   a1 = ztc(relu(adj @ (a0@W1+b1) / 100))
//   out = (a1 @ W_out + b_out) * node_mask
// where ztc zeroes column 0. No transcendentals needed: logmap0∘expmap0 = id
// on tangent vectors (clamps only matter for row-norms < ~3e-4, which do not
// occur at these input scales).

static constexpr int BATCH = 512;
static constexpr int NNODE = 256;
static constexpr int H     = 64;
// BN = 131072 rows

__device__ float g_bufA[131072 * 64];
__device__ float g_bufB[131072 * 64];

// ---------------------------------------------------------------------------
// Row-block GEMM: C[M x 64] = A[M x 64] @ W[64 x 64]  (+ epilogue)
//   EPI 0: zero column 0 of result (ztc)
//   EPI 1: add bias
//   EPI 2: add bias, multiply by per-row mask
// Block: 256 threads, 64 rows x 64 cols tile, 4x4 per-thread register tile.
// ---------------------------------------------------------------------------
template<int EPI>
__global__ void __launch_bounds__(256)
gemm_rowwise(const float* __restrict__ A, const float* __restrict__ W,
             const float* __restrict__ bias, const float* __restrict__ mask,
             float* __restrict__ C)
{
    __shared__ float As[64][65];     // padded: conflict-free column reads
    __shared__ float Ws[64 * 64];    // flat, row k major, float4-readable
    __shared__ float bs[64];

    const int  tid  = threadIdx.x;
    const long row0 = (long)blockIdx.x * 64;

    // A tile is a contiguous 64x64 block (K == full row width)
    const float4* __restrict__ Ag = reinterpret_cast<const float4*>(A + row0 * 64);
    #pragma unroll
    for (int i = 0; i < 4; i++) {
        int idx = tid + i * 256;
        float4 v = Ag[idx];
        int r = idx >> 4;
        int c = (idx & 15) << 2;
        As[r][c]   = v.x; As[r][c+1] = v.y;
        As[r][c+2] = v.z; As[r][c+3] = v.w;
    }
    const float4* __restrict__ Wg = reinterpret_cast<const float4*>(W);
    #pragma unroll
    for (int i = 0; i < 4; i++)
        reinterpret_cast<float4*>(Ws)[tid + i * 256] = Wg[tid + i * 256];
    if (EPI >= 1 && tid < 64) bs[tid] = bias[tid];
    __syncthreads();

    const int tx = tid & 15;   // column group: cols tx*4 .. tx*4+3
    const int ty = tid >> 4;   // row group:    rows ty*4 .. ty*4+3

    float acc[4][4];
    #pragma unroll
    for (int i = 0; i < 4; i++)
        #pragma unroll
        for (int j = 0; j < 4; j++) acc[i][j] = 0.f;

    #pragma unroll 16
    for (int k = 0; k < 64; k++) {
        float4 w = *reinterpret_cast<const float4*>(&Ws[k * 64 + tx * 4]);
        #pragma unroll
        for (int i = 0; i < 4; i++) {
            float a = As[ty * 4 + i][k];
            acc[i][0] += a * w.x;
            acc[i][1] += a * w.y;
            acc[i][2] += a * w.z;
            acc[i][3] += a * w.w;
        }
    }

    #pragma unroll
    for (int i = 0; i < 4; i++) {
        long row = row0 + ty * 4 + i;
        float4 v;
        v.x = acc[i][0]; v.y = acc[i][1]; v.z = acc[i][2]; v.w = acc[i][3];
        if (EPI >= 1) {
            v.x += bs[tx * 4];     v.y += bs[tx * 4 + 1];
            v.z += bs[tx * 4 + 2]; v.w += bs[tx * 4 + 3];
        }
        if (EPI == 0) { if (tx == 0) v.x = 0.f; }
        if (EPI == 2) {
            float m = mask[row];
            v.x *= m; v.y *= m; v.z *= m; v.w *= m;
        }
        *reinterpret_cast<float4*>(&C[row * 64 + tx * 4]) = v;
    }
}

// ---------------------------------------------------------------------------
// Batched aggregation GEMM with fused epilogue:
//   C[b][i][h] = ztc( relu( (1/100) * sum_j adj[b][i][j] * S[b][j][h] ) )
// Block: 256 threads, 128 rows x 64 cols (full H) tile, K-tiles of 32,
// 8x4 per-thread register tile. Grid (2 row-tiles, 512 batches).
// ---------------------------------------------------------------------------
__global__ void __launch_bounds__(256)
gemm_adj(const float* __restrict__ adj, const float* __restrict__ S,
         float* __restrict__ C)
{
    __shared__ float As[128][33];    // adj tile, pitch 33: conflict-free
    __shared__ float Ss[32 * 64];    // S tile, flat, float4-readable

    const int tid  = threadIdx.x;
    const int b    = blockIdx.y;
    const int row0 = blockIdx.x * 128;
    const float* __restrict__ adjb = adj + (size_t)b * 256 * 256;
    const float* __restrict__ Sb   = S   + (size_t)b * 256 * 64;

    const int tx = tid & 15;   // cols tx*4 .. tx*4+3
    const int ty = tid >> 4;   // rows ty*8 .. ty*8+7

    float acc[8][4];
    #pragma unroll
    for (int i = 0; i < 8; i++)
        #pragma unroll
        for (int j = 0; j < 4; j++) acc[i][j] = 0.f;

    for (int k0 = 0; k0 < 256; k0 += 32) {
        // adj tile: 128 rows x 32 cols; 8 lanes cover one 128B row segment
        #pragma unroll
        for (int i = 0; i < 4; i++) {
            int idx = tid + i * 256;
            int r = idx >> 3;
            int c = (idx & 7) << 2;
            float4 v = *reinterpret_cast<const float4*>(
                &adjb[(size_t)(row0 + r) * 256 + k0 + c]);
            As[r][c]   = v.x; As[r][c+1] = v.y;
            As[r][c+2] = v.z; As[r][c+3] = v.w;
        }
        // S tile: 32 x 64 contiguous
        #pragma unroll
        for (int i = 0; i < 2; i++) {
            int idx = tid + i * 256;
            reinterpret_cast<float4*>(Ss)[idx] =
                *reinterpret_cast<const float4*>(&Sb[(size_t)k0 * 64 + idx * 4]);
        }
        __syncthreads();

        #pragma unroll 8
        for (int kk = 0; kk < 32; kk++) {
            float4 w = *reinterpret_cast<const float4*>(&Ss[kk * 64 + tx * 4]);
            #pragma unroll
            for (int i = 0; i < 8; i++) {
                float a = As[ty * 8 + i][kk];
                acc[i][0] += a * w.x;
                acc[i][1] += a * w.y;
                acc[i][2] += a * w.z;
                acc[i][3] += a * w.w;
            }
        }
        __syncthreads();
    }

    const float inv = 1.0f / 100.0f;
    #pragma unroll
    for (int i = 0; i < 8; i++) {
        int row = row0 + ty * 8 + i;
        float4 v;
        v.x = fmaxf(acc[i][0] * inv, 0.f);
        v.y = fmaxf(acc[i][1] * inv, 0.f);
        v.z = fmaxf(acc[i][2] * inv, 0.f);
        v.w = fmaxf(acc[i][3] * inv, 0.f);
        if (tx == 0) v.x = 0.f;   // proj_tan0
        *reinterpret_cast<float4*>(&C[((size_t)b * 256 + row) * 64 + tx * 4]) = v;
    }
}

// ---------------------------------------------------------------------------
// Input order (metadata): x, adj, node_mask, W_embed, W0, b0, W1, b1, W_out, b_out
// Output: (512, 256, 64) float32
// ---------------------------------------------------------------------------
extern "C" void kernel_launch(void* const* d_in, const int* in_sizes, int n_in,
                              void* d_out, int out_size)
{
    const float* x       = (const float*)d_in[0];
    const float* adj     = (const float*)d_in[1];
    const float* nmask   = (const float*)d_in[2];
    const float* W_embed = (const float*)d_in[3];
    const float* W0      = (const float*)d_in[4];
    const float* b0      = (const float*)d_in[5];
    const float* W1      = (const float*)d_in[6];
    const float* b1      = (const float*)d_in[7];
    const float* W_out   = (const float*)d_in[8];
    const float* b_out   = (const float*)d_in[9];
    float* out = (float*)d_out;

    float* bufA = nullptr;
    float* bufB = nullptr;
    cudaGetSymbolAddress((void**)&bufA, g_bufA);
    cudaGetSymbolAddress((void**)&bufB, g_bufB);

    dim3 blk(256);
    dim3 grdR(131072 / 64);        // 2048 blocks, 64 rows each
    dim3 grdA(2, BATCH);           // 2 row-tiles x 512 batches

    // t0 = ztc(x @ W_embed)
    gemm_rowwise<0><<<grdR, blk>>>(x, W_embed, nullptr, nullptr, bufA);
    // s0 = t0 @ W0 + b0
    gemm_rowwise<1><<<grdR, blk>>>(bufA, W0, b0, nullptr, bufB);
    // a0 = ztc(relu(adj @ s0 / 100))
    gemm_adj<<<grdA, blk>>>(adj, bufB, bufA);
    // s1 = a0 @ W1 + b1
    gemm_rowwise<1><<<grdR, blk>>>(bufA, W1, b1, nullptr, bufB);
    // a1 = ztc(relu(adj @ s1 / 100))
    gemm_adj<<<grdA, blk>>>(adj, bufB, bufA);
    // out = (a1 @ W_out + b_out) * node_mask
    gemm_rowwise<2><<<grdR, blk>>>(bufA, W_out, b_out, nmask, out);
}

// round 2
// speedup vs baseline: 1.3622x; 1.3622x over previous
#include <cuda_runtime.h>
#include <cstdint>

// Fully fused HGCN, one CTA per batch element (grid = 512, block = 256).
// Pipeline (ztc folded into weights: zeroing row 0 of W ≡ zeroing col 0 of input):
//   t0 = x @ We                      (stream x,   B = We)
//   s0 = t0 @ W0z + b0               (smem A,     B = W0 row0-zeroed)
//   a0 = relu(adj @ s0 / 100)        (stream adj, B = s0)
//   s1 = a0 @ W1z + b1
//   a1 = relu(adj @ s1 / 100)
//   out = (a1 @ Woz + b_out) * mask
// All activations live in SMEM as tf32-rounded fp32; mma.sync m16n8k8 tf32.

static constexpr int NP   = 256;   // nodes per batch
static constexpr int HD   = 64;    // hidden
static constexpr int PA   = 76;    // act/W pitch: 76 % 32 == 12 -> both frag
                                   // patterns (12g+t and 12t+g) conflict-free
static constexpr int PADJ = 20;    // adj tile pitch: 20g+t conflict-free
static constexpr int KT   = 16;    // streamed K-tile

static constexpr int SMEM_FLOATS = 2 * NP * PA       // actA, actB
                                 + 2 * NP * PADJ     // adj double buffer
                                 + HD * PA           // weight buffer
                                 + HD;               // bias
static constexpr size_t SMEM_BYTES = SMEM_FLOATS * sizeof(float);

__device__ __forceinline__ uint32_t f2tf(float f) {
    uint32_t u;
    asm("cvt.rna.tf32.f32 %0, %1;" : "=r"(u) : "f"(f));
    return u;
}

__device__ __forceinline__ void mma8(float* c, const uint32_t* a,
                                     uint32_t b0, uint32_t b1) {
    asm volatile(
        "mma.sync.aligned.m16n8k8.row.col.f32.tf32.tf32.f32 "
        "{%0,%1,%2,%3}, {%4,%5,%6,%7}, {%8,%9}, {%0,%1,%2,%3};\n"
        : "+f"(c[0]), "+f"(c[1]), "+f"(c[2]), "+f"(c[3])
        : "r"(a[0]), "r"(a[1]), "r"(a[2]), "r"(a[3]), "r"(b0), "r"(b1));
}

__device__ __forceinline__ void cpa16(float* dst, const float* src) {
    uint32_t d = (uint32_t)__cvta_generic_to_shared(dst);
    asm volatile("cp.async.ca.shared.global [%0], [%1], 16;\n"
                 :: "r"(d), "l"(src));
}

__device__ __forceinline__ void zero_acc(float acc[2][8][4]) {
    #pragma unroll
    for (int i = 0; i < 2; i++)
        #pragma unroll
        for (int j = 0; j < 8; j++)
            #pragma unroll
            for (int r = 0; r < 4; r++) acc[i][j][r] = 0.f;
}

// Load 64x64 weight into smem (pitch PA), RNA-rounded to tf32, optionally
// zeroing row 0 (folds the ztc of the producing stage). Optional bias.
__device__ __forceinline__ void load_weight(const float* __restrict__ W,
                                            const float* __restrict__ bias,
                                            bool zr0, float* Wb, float* bs,
                                            int tid) {
    for (int i = tid; i < HD * HD; i += 256) {
        int r = i >> 6, c = i & 63;
        float v = W[i];
        if (zr0 && r == 0) v = 0.f;
        Wb[r * PA + c] = __uint_as_float(f2tf(v));
    }
    if (bias && tid < HD) bs[tid] = bias[tid];
}

// C[256x64] += A_smem[256x64] @ B_smem[64x64]; warp handles rows [m_base, m_base+32)
__device__ __forceinline__ void gemm_smemA(const float* __restrict__ A,
                                           const float* __restrict__ B,
                                           float acc[2][8][4],
                                           int m_base, int g, int t) {
    #pragma unroll
    for (int k0 = 0; k0 < HD; k0 += 8) {
        uint32_t a[2][4];
        #pragma unroll
        for (int i = 0; i < 2; i++) {
            const float* ap = A + (m_base + i * 16 + g) * PA + k0 + t;
            a[i][0] = __float_as_uint(ap[0]);
            a[i][1] = __float_as_uint(ap[8 * PA]);
            a[i][2] = __float_as_uint(ap[4]);
            a[i][3] = __float_as_uint(ap[8 * PA + 4]);
        }
        #pragma unroll
        for (int j = 0; j < 8; j++) {
            uint32_t b0 = __float_as_uint(B[(k0 + t) * PA + j * 8 + g]);
            uint32_t b1 = __float_as_uint(B[(k0 + t + 4) * PA + j * 8 + g]);
            mma8(acc[0][j], a[0], b0, b1);
            mma8(acc[1][j], a[1], b0, b1);
        }
    }
}

// C[256x64] += A_gmem[256xK] @ B_smem[Kx64], A streamed via cp.async
// double-buffered KT-wide tiles. A fragments RNA-rounded at load.
__device__ __forceinline__ void gemm_streamA(const float* __restrict__ gA,
                                             int lda, int K,
                                             const float* __restrict__ B,
                                             float* adjs, float acc[2][8][4],
                                             int m_base, int g, int t, int tid) {
    const int nchunk = K / KT;
    auto prefetch = [&](int c, int buf) {
        float* dst = adjs + buf * NP * PADJ;
        #pragma unroll
        for (int i = 0; i < 4; i++) {
            int id = tid + i * 256;
            int r = id >> 2, s = id & 3;
            cpa16(dst + r * PADJ + s * 4,
                  gA + (size_t)r * lda + c * KT + s * 4);
        }
        asm volatile("cp.async.commit_group;\n");
    };
    prefetch(0, 0);
    for (int c = 0; c < nchunk; c++) {
        int buf = c & 1;
        if (c + 1 < nchunk) {
            prefetch(c + 1, buf ^ 1);
            asm volatile("cp.async.wait_group 1;\n");
        } else {
            asm volatile("cp.async.wait_group 0;\n");
        }
        __syncthreads();
        const float* At = adjs + buf * NP * PADJ;
        #pragma unroll
        for (int kk = 0; kk < KT; kk += 8) {
            uint32_t a[2][4];
            #pragma unroll
            for (int i = 0; i < 2; i++) {
                const float* ap = At + (m_base + i * 16 + g) * PADJ + kk + t;
                a[i][0] = f2tf(ap[0]);
                a[i][1] = f2tf(ap[8 * PADJ]);
                a[i][2] = f2tf(ap[4]);
                a[i][3] = f2tf(ap[8 * PADJ + 4]);
            }
            const int k0 = c * KT + kk;
            #pragma unroll
            for (int j = 0; j < 8; j++) {
                uint32_t b0 = __float_as_uint(B[(k0 + t) * PA + j * 8 + g]);
                uint32_t b1 = __float_as_uint(B[(k0 + t + 4) * PA + j * 8 + g]);
                mma8(acc[0][j], a[0], b0, b1);
                mma8(acc[1][j], a[1], b0, b1);
            }
        }
        __syncthreads();
    }
}

// EPI: 0 = plain, 1 = +bias, 2 = relu(acc/100). Result stored tf32-rounded.
template <int EPI>
__device__ __forceinline__ void store_acc_smem(float acc[2][8][4], float* dst,
                                               const float* bs,
                                               int m_base, int g, int t) {
    #pragma unroll
    for (int i = 0; i < 2; i++)
        #pragma unroll
        for (int j = 0; j < 8; j++)
            #pragma unroll
            for (int r = 0; r < 4; r++) {
                int row = m_base + i * 16 + g + ((r >> 1) << 3);
                int col = j * 8 + 2 * t + (r & 1);
                float v = acc[i][j][r];
                if (EPI == 1) v += bs[col];
                if (EPI == 2) v = fmaxf(v * 0.01f, 0.f);
                dst[row * PA + col] = __uint_as_float(f2tf(v));
            }
}

__device__ __forceinline__ void store_out(float acc[2][8][4],
                                          float* __restrict__ out,
                                          const float* bs,
                                          const float* __restrict__ maskrow,
                                          int m_base, int g, int t) {
    #pragma unroll
    for (int i = 0; i < 2; i++) {
        float mv0 = maskrow[m_base + i * 16 + g];
        float mv1 = maskrow[m_base + i * 16 + g + 8];
        #pragma unroll
        for (int j = 0; j < 8; j++)
            #pragma unroll
            for (int r = 0; r < 4; r++) {
                int row = m_base + i * 16 + g + ((r >> 1) << 3);
                int col = j * 8 + 2 * t + (r & 1);
                float v = acc[i][j][r] + bs[col];
                v *= (r >= 2 ? mv1 : mv0);
                out[(size_t)row * HD + col] = v;
            }
    }
}

__global__ void __launch_bounds__(256, 1)
hgcn_fused(const float* __restrict__ x, const float* __restrict__ adj,
           const float* __restrict__ nmask,
           const float* __restrict__ W_embed,
           const float* __restrict__ W0, const float* __restrict__ b0,
           const float* __restrict__ W1, const float* __restrict__ b1,
           const float* __restrict__ W_out, const float* __restrict__ b_out,
           float* __restrict__ out) {
    extern __shared__ float sm[];
    float* actA = sm;
    float* actB = actA + NP * PA;
    float* adjs = actB + NP * PA;
    float* Wb   = adjs + 2 * NP * PADJ;
    float* bs   = Wb + HD * PA;

    const int tid  = threadIdx.x;
    const int lane = tid & 31;
    const int g = lane >> 2, t = lane & 3;
    const int m_base = (tid >> 5) * 32;
    const int b = blockIdx.x;

    float acc[2][8][4];

    // Stage 1: t0 = x @ We -> actA
    load_weight(W_embed, nullptr, false, Wb, bs, tid);
    __syncthreads();
    zero_acc(acc);
    gemm_streamA(x + (size_t)b * NP * HD, HD, HD, Wb, adjs, acc, m_base, g, t, tid);
    store_acc_smem<0>(acc, actA, bs, m_base, g, t);
    __syncthreads();

    // Stage 2: s0 = t0 @ W0z + b0 -> actB
    load_weight(W0, b0, true, Wb, bs, tid);
    __syncthreads();
    zero_acc(acc);
    gemm_smemA(actA, Wb, acc, m_base, g, t);
    store_acc_smem<1>(acc, actB, bs, m_base, g, t);
    __syncthreads();

    // Stage 3: a0 = relu(adj @ s0 / 100) -> actA
    zero_acc(acc);
    gemm_streamA(adj + (size_t)b * NP * NP, NP, NP, actB, adjs, acc, m_base, g, t, tid);
    store_acc_smem<2>(acc, actA, bs, m_base, g, t);
    __syncthreads();

    // Stage 4: s1 = a0 @ W1z + b1 -> actB
    load_weight(W1, b1, true, Wb, bs, tid);
    __syncthreads();
    zero_acc(acc);
    gemm_smemA(actA, Wb, acc, m_base, g, t);
    store_acc_smem<1>(acc, actB, bs, m_base, g, t);
    __syncthreads();

    // Stage 5: a1 = relu(adj @ s1 / 100) -> actA
    zero_acc(acc);
    gemm_streamA(adj + (size_t)b * NP * NP, NP, NP, actB, adjs, acc, m_base, g, t, tid);
    store_acc_smem<2>(acc, actA, bs, m_base, g, t);
    __syncthreads();

    // Stage 6: out = (a1 @ Woz + b_out) * mask
    load_weight(W_out, b_out, true, Wb, bs, tid);
    __syncthreads();
    zero_acc(acc);
    gemm_smemA(actA, Wb, acc, m_base, g, t);
    store_out(acc, out + (size_t)b * NP * HD, bs, nmask + (size_t)b * NP,
              m_base, g, t);
}

extern "C" void kernel_launch(void* const* d_in, const int* in_sizes, int n_in,
                              void* d_out, int out_size) {
    const float* x       = (const float*)d_in[0];
    const float* adj     = (const float*)d_in[1];
    const float* nmask   = (const float*)d_in[2];
    const float* W_embed = (const float*)d_in[3];
    const float* W0      = (const float*)d_in[4];
    const float* b0      = (const float*)d_in[5];
    const float* W1      = (const float*)d_in[6];
    const float* b1      = (const float*)d_in[7];
    const float* W_out   = (const float*)d_in[8];
    const float* b_out   = (const float*)d_in[9];
    float* out = (float*)d_out;

    // Persisted from the first (correctness) call; harmless if it no-ops later.
    cudaFuncSetAttribute(hgcn_fused, cudaFuncAttributeMaxDynamicSharedMemorySize,
                         (int)SMEM_BYTES);

    hgcn_fused<<<512, 256, SMEM_BYTES>>>(x, adj, nmask, W_embed, W0, b0,
                                         W1, b1, W_out, b_out, out);
}

// round 3
// speedup vs baseline: 2.0538x; 1.5077x over previous
#include <cuda_runtime.h>
#include <cstdint>

// HGCN (math-reduced) as 3 wide GEMM kernels + tiny weight-combine:
//   W01 = We @ W0z                      (kW, 64x64x64)
//   s0  = x @ W01 + b0                  (kRow, M=131072)
//   s1  = relu(adj@s0/100) @ W1z + b1   (kAdj<0>, fused epilogue GEMM)
//   out = (relu(adj@s1/100) @ Woz + b_out) * mask   (kAdj<1>)
// ztc folded into weights (zero row 0). tf32 mma.sync m16n8k8 throughout.

static constexpr int NP   = 256;
static constexpr int HD   = 64;
static constexpr int PW   = 72;  // K-major B pitch: 72%32==8 -> t*8+g conflict-free
static constexpr int PADJ = 36;  // adj tile pitch:  36%32==4 -> 4g+t conflict-free
static constexpr int PC   = 68;  // A/C smem pitch:  68%32==4 conflict-free
static constexpr int KT   = 32;

__device__ float g_bufA[131072 * 64];
__device__ float g_bufB[131072 * 64];
__device__ float g_W01[64 * 64];

static constexpr size_t SMEM_ADJ = (HD * PW + HD + 2 * KT * PW + 2 * 128 * PADJ) * 4;
static constexpr size_t SMEM_ROW = (HD * PW + HD + 128 * PC) * 4;

__device__ __forceinline__ uint32_t f2tf(float f) {
    uint32_t u;
    asm("cvt.rna.tf32.f32 %0, %1;" : "=r"(u) : "f"(f));
    return u;
}

__device__ __forceinline__ void mma8(float* c, const uint32_t* a,
                                     uint32_t b0, uint32_t b1) {
    asm volatile(
        "mma.sync.aligned.m16n8k8.row.col.f32.tf32.tf32.f32 "
        "{%0,%1,%2,%3}, {%4,%5,%6,%7}, {%8,%9}, {%0,%1,%2,%3};\n"
        : "+f"(c[0]), "+f"(c[1]), "+f"(c[2]), "+f"(c[3])
        : "r"(a[0]), "r"(a[1]), "r"(a[2]), "r"(a[3]), "r"(b0), "r"(b1));
}

__device__ __forceinline__ void cpa16(float* dst, const float* src) {
    uint32_t d = (uint32_t)__cvta_generic_to_shared(dst);
    asm volatile("cp.async.ca.shared.global [%0], [%1], 16;\n" :: "r"(d), "l"(src));
}

// ---------------------------------------------------------------------------
// kW: W01 = We @ (W0 with row 0 zeroed)   [skip k=0 term]
// ---------------------------------------------------------------------------
__global__ void __launch_bounds__(256)
kW(const float* __restrict__ We, const float* __restrict__ W0,
   float* __restrict__ W01) {
    int id = blockIdx.x * 256 + threadIdx.x;   // 4096 outputs
    int r = id >> 6, c = id & 63;
    float s = 0.f;
    #pragma unroll 8
    for (int k = 1; k < 64; k++) s += We[r * 64 + k] * W0[k * 64 + c];
    W01[id] = s;
}

// ---------------------------------------------------------------------------
// kRow: C[row0+128][64] = round_tf32( X @ W + bias ), X raw fp32 in gmem.
// ---------------------------------------------------------------------------
__global__ void __launch_bounds__(256, 2)
kRow(const float* __restrict__ X, const float* __restrict__ W,
     const float* __restrict__ bias, float* __restrict__ out) {
    extern __shared__ float sm[];
    float* Wt = sm;
    float* bs = Wt + HD * PW;
    float* Xs = bs + HD;

    const int tid = threadIdx.x;
    const int lane = tid & 31, w = tid >> 5;
    const int g = lane >> 2, t = lane & 3;
    const int mrow = w * 16;
    const long row0 = (long)blockIdx.x * 128;

    // async-stage X tile 128x64 (pitch PC)
    #pragma unroll
    for (int i = 0; i < 8; i++) {
        int idx = tid + i * 256;
        int r = idx >> 4, c4 = (idx & 15) << 2;
        cpa16(Xs + r * PC + c4, X + (row0 + r) * 64 + c4);
    }
    asm volatile("cp.async.commit_group;\n");

    for (int i = tid; i < HD * HD; i += 256) {
        int r = i >> 6, c = i & 63;
        Wt[r * PW + c] = __uint_as_float(f2tf(W[i]));
    }
    if (tid < HD) bs[tid] = bias[tid];

    asm volatile("cp.async.wait_group 0;\n");
    __syncthreads();

    float acc[8][4];
    #pragma unroll
    for (int j = 0; j < 8; j++)
        #pragma unroll
        for (int r = 0; r < 4; r++) acc[j][r] = 0.f;

    #pragma unroll
    for (int k0 = 0; k0 < 64; k0 += 8) {
        const float* ap = Xs + (mrow + g) * PC + k0 + t;
        uint32_t a[4];
        a[0] = f2tf(ap[0]);
        a[1] = f2tf(ap[8 * PC]);
        a[2] = f2tf(ap[4]);
        a[3] = f2tf(ap[8 * PC + 4]);
        #pragma unroll
        for (int j = 0; j < 8; j++) {
            uint32_t b0 = __float_as_uint(Wt[(k0 + t) * PW + j * 8 + g]);
            uint32_t b1 = __float_as_uint(Wt[(k0 + t + 4) * PW + j * 8 + g]);
            mma8(acc[j], a, b0, b1);
        }
    }

    #pragma unroll
    for (int j = 0; j < 8; j++)
        #pragma unroll
        for (int r = 0; r < 4; r++) {
            int row = mrow + g + ((r >> 1) << 3);
            int col = j * 8 + 2 * t + (r & 1);
            float v = acc[j][r] + bs[col];
            out[(row0 + row) * 64 + col] = __uint_as_float(f2tf(v));
        }
}

// ---------------------------------------------------------------------------
// kAdj: per (mtile, batch):
//   T = round_tf32( relu( adj[b][row0:+128][:] @ S[b] / 100 ) )   (mainloop)
//   U = T @ Wz + bias                                             (smem GEMM)
//   MASKED=0: store round_tf32(U) ; MASKED=1: store fp32 U*mask
// S rows are already tf32-rounded by the producer; adj/x rounded at frag load.
// ---------------------------------------------------------------------------
template <int MASKED>
__global__ void __launch_bounds__(256, 2)
kAdj(const float* __restrict__ adj, const float* __restrict__ S,
     const float* __restrict__ W, const float* __restrict__ bias,
     const float* __restrict__ nmask, float* __restrict__ out) {
    extern __shared__ float sm[];
    float* Wt   = sm;                  // 64 x PW (tf32, row0 zeroed)
    float* bs   = Wt + HD * PW;        // 64
    float* Bs   = bs + HD;             // 2 x KT x PW
    float* adjs = Bs + 2 * KT * PW;    // 2 x 128 x PADJ
    float* Csm  = adjs;                // reused after mainloop (128 x PC fits)

    const int tid = threadIdx.x;
    const int lane = tid & 31, w = tid >> 5;
    const int g = lane >> 2, t = lane & 3;
    const int b = blockIdx.y;
    const int row0 = blockIdx.x * 128;
    const int mrow = w * 16;

    const float* adjb = adj + ((size_t)b * NP + row0) * NP;
    const float* Sb   = S + (size_t)b * NP * HD;

    auto prefetch = [&](int c, int buf) {
        float* ad = adjs + buf * 128 * PADJ;
        #pragma unroll
        for (int i = 0; i < 4; i++) {
            int idx = tid + i * 256;
            int r = idx >> 3, s4 = (idx & 7) << 2;
            cpa16(ad + r * PADJ + s4, adjb + (size_t)r * NP + c * KT + s4);
        }
        float* bd = Bs + buf * KT * PW;
        #pragma unroll
        for (int i = 0; i < 2; i++) {
            int idx = tid + i * 256;
            int r = idx >> 4, s4 = (idx & 15) << 2;
            cpa16(bd + r * PW + s4, Sb + (size_t)(c * KT + r) * HD + s4);
        }
        asm volatile("cp.async.commit_group;\n");
    };

    prefetch(0, 0);

    for (int i = tid; i < HD * HD; i += 256) {
        int r = i >> 6, c = i & 63;
        float v = (r == 0) ? 0.f : W[i];        // ztc fold
        Wt[r * PW + c] = __uint_as_float(f2tf(v));
    }
    if (tid < HD) bs[tid] = bias[tid];

    float acc[8][4];
    #pragma unroll
    for (int j = 0; j < 8; j++)
        #pragma unroll
        for (int r = 0; r < 4; r++) acc[j][r] = 0.f;

    const int NCH = NP / KT;   // 8
    for (int c = 0; c < NCH; c++) {
        int buf = c & 1;
        if (c + 1 < NCH) {
            prefetch(c + 1, buf ^ 1);
            asm volatile("cp.async.wait_group 1;\n");
        } else {
            asm volatile("cp.async.wait_group 0;\n");
        }
        __syncthreads();
        const float* At = adjs + buf * 128 * PADJ;
        const float* Bt = Bs + buf * KT * PW;
        #pragma unroll
        for (int kk = 0; kk < KT; kk += 8) {
            const float* ap = At + (mrow + g) * PADJ + kk + t;
            uint32_t a[4];
            a[0] = f2tf(ap[0]);
            a[1] = f2tf(ap[8 * PADJ]);
            a[2] = f2tf(ap[4]);
            a[3] = f2tf(ap[8 * PADJ + 4]);
            #pragma unroll
            for (int j = 0; j < 8; j++) {
                uint32_t b0 = __float_as_uint(Bt[(kk + t) * PW + j * 8 + g]);
                uint32_t b1 = __float_as_uint(Bt[(kk + t + 4) * PW + j * 8 + g]);
                mma8(acc[j], a, b0, b1);
            }
        }
        __syncthreads();
    }

    // T = round(relu(acc/100)) -> Csm
    #pragma unroll
    for (int j = 0; j < 8; j++)
        #pragma unroll
        for (int r = 0; r < 4; r++) {
            int row = mrow + g + ((r >> 1) << 3);
            int col = j * 8 + 2 * t + (r & 1);
            float v = fmaxf(acc[j][r] * 0.01f, 0.f);
            Csm[row * PC + col] = __uint_as_float(f2tf(v));
        }
    __syncthreads();

    // U = T @ Wz
    #pragma unroll
    for (int j = 0; j < 8; j++)
        #pragma unroll
        for (int r = 0; r < 4; r++) acc[j][r] = 0.f;

    #pragma unroll
    for (int k0 = 0; k0 < 64; k0 += 8) {
        const float* ap = Csm + (mrow + g) * PC + k0 + t;
        uint32_t a[4];
        a[0] = __float_as_uint(ap[0]);
        a[1] = __float_as_uint(ap[8 * PC]);
        a[2] = __float_as_uint(ap[4]);
        a[3] = __float_as_uint(ap[8 * PC + 4]);
        #pragma unroll
        for (int j = 0; j < 8; j++) {
            uint32_t b0 = __float_as_uint(Wt[(k0 + t) * PW + j * 8 + g]);
            uint32_t b1 = __float_as_uint(Wt[(k0 + t + 4) * PW + j * 8 + g]);
            mma8(acc[j], a, b0, b1);
        }
    }

    float mv0 = 1.f, mv1 = 1.f;
    if (MASKED) {
        const float* mrowp = nmask + (size_t)b * NP + row0;
        mv0 = mrowp[mrow + g];
        mv1 = mrowp[mrow + g + 8];
    }
    float* outb = out + ((size_t)b * NP + row0) * HD;
    #pragma unroll
    for (int j = 0; j < 8; j++)
        #pragma unroll
        for (int r = 0; r < 4; r++) {
            int row = mrow + g + ((r >> 1) << 3);
            int col = j * 8 + 2 * t + (r & 1);
            float v = acc[j][r] + bs[col];
            if (MASKED) {
                v *= (r >= 2 ? mv1 : mv0);
                outb[(size_t)row * HD + col] = v;
            } else {
                outb[(size_t)row * HD + col] = __uint_as_float(f2tf(v));
            }
        }
}

// ---------------------------------------------------------------------------
extern "C" void kernel_launch(void* const* d_in, const int* in_sizes, int n_in,
                              void* d_out, int out_size) {
    const float* x       = (const float*)d_in[0];
    const float* adj     = (const float*)d_in[1];
    const float* nmask   = (const float*)d_in[2];
    const float* W_embed = (const float*)d_in[3];
    const float* W0      = (const float*)d_in[4];
    const float* b0      = (const float*)d_in[5];
    const float* W1      = (const float*)d_in[6];
    const float* b1      = (const float*)d_in[7];
    const float* W_out   = (const float*)d_in[8];
    const float* b_out   = (const float*)d_in[9];
    float* out = (float*)d_out;

    float *bufA = nullptr, *bufB = nullptr, *w01 = nullptr;
    cudaGetSymbolAddress((void**)&bufA, g_bufA);
    cudaGetSymbolAddress((void**)&bufB, g_bufB);
    cudaGetSymbolAddress((void**)&w01, g_W01);

    cudaFuncSetAttribute(kRow, cudaFuncAttributeMaxDynamicSharedMemorySize,
                         (int)SMEM_ROW);
    cudaFuncSetAttribute(kAdj<0>, cudaFuncAttributeMaxDynamicSharedMemorySize,
                         (int)SMEM_ADJ);
    cudaFuncSetAttribute(kAdj<1>, cudaFuncAttributeMaxDynamicSharedMemorySize,
                         (int)SMEM_ADJ);

    kW<<<16, 256>>>(W_embed, W0, w01);
    kRow<<<1024, 256, SMEM_ROW>>>(x, w01, b0, bufA);
    kAdj<0><<<dim3(2, 512), 256, SMEM_ADJ>>>(adj, bufA, W1, b1, nullptr, bufB);
    kAdj<1><<<dim3(2, 512), 256, SMEM_ADJ>>>(adj, bufB, W_out, b_out, nmask, out);
}

// round 4
// speedup vs baseline: 2.1723x; 1.0577x over previous
#include <cuda_runtime.h>
#include <cstdint>

// HGCN (math-reduced) as 3 GEMM kernels + weight-prep:
//   prep: W01 = tf32(We @ W0z), W1z/Woz = tf32(row0-zeroed W1/W_out)
//   s0  = x @ W01 + b0                              (kRow)
//   s1  = relu(adj@s0/100) @ W1z + b1               (kAdj<0>)
//   out = (relu(adj@s1/100) @ Woz + b_out) * mask   (kAdj<1>)
// tf32 mma.sync m16n8k8; warp tile m32xn32; 3 CTAs/SM.

static constexpr int NP   = 256;
static constexpr int HD   = 64;
static constexpr int PW   = 72;  // B pitch: 72%32==8 -> t*8+g conflict-free
static constexpr int PADJ = 36;  // A pitch: 36%32==4 -> 4g+t conflict-free
static constexpr int PC   = 68;  // epilogue A pitch: 68%32==4 conflict-free
static constexpr int KT   = 32;

__device__ float g_bufA[131072 * 64];
__device__ float g_bufB[131072 * 64];
__device__ float g_Wpre[3 * 64 * 64];   // [0]=W01, [1]=W1z, [2]=Woz (tf32)

static constexpr size_t SMEM_ADJ = (HD * PW + HD + 2 * KT * PW + 2 * 128 * PADJ) * 4;
static constexpr size_t SMEM_ROW = (HD * PW + HD + 128 * PC) * 4;

__device__ __forceinline__ uint32_t f2tf(float f) {
    uint32_t u;
    asm("cvt.rna.tf32.f32 %0, %1;" : "=r"(u) : "f"(f));
    return u;
}

__device__ __forceinline__ void mma8(float* c, const uint32_t* a,
                                     uint32_t b0, uint32_t b1) {
    asm volatile(
        "mma.sync.aligned.m16n8k8.row.col.f32.tf32.tf32.f32 "
        "{%0,%1,%2,%3}, {%4,%5,%6,%7}, {%8,%9}, {%0,%1,%2,%3};\n"
        : "+f"(c[0]), "+f"(c[1]), "+f"(c[2]), "+f"(c[3])
        : "r"(a[0]), "r"(a[1]), "r"(a[2]), "r"(a[3]), "r"(b0), "r"(b1));
}

__device__ __forceinline__ void cpa16(float* dst, const float* src) {
    uint32_t d = (uint32_t)__cvta_generic_to_shared(dst);
    asm volatile("cp.async.ca.shared.global [%0], [%1], 16;\n" :: "r"(d), "l"(src));
}

// ---------------------------------------------------------------------------
// kPrep: 48 blocks x 256. ids 0..4095 -> W01 = tf32(We @ W0z);
//        4096..8191 -> W1z; 8192..12287 -> Woz.
// ---------------------------------------------------------------------------
__global__ void __launch_bounds__(256)
kPrep(const float* __restrict__ We, const float* __restrict__ W0,
      const float* __restrict__ W1, const float* __restrict__ Wo,
      float* __restrict__ Wpre) {
    int id = blockIdx.x * 256 + threadIdx.x;
    int which = id >> 12;
    int li = id & 4095;
    int r = li >> 6, c = li & 63;
    float v;
    if (which == 0) {
        float s = 0.f;
        #pragma unroll 8
        for (int k = 1; k < 64; k++) s += We[r * 64 + k] * W0[k * 64 + c];
        v = s;
    } else {
        const float* W = (which == 1) ? W1 : Wo;
        v = (r == 0) ? 0.f : W[li];
    }
    Wpre[id] = __uint_as_float(f2tf(v));
}

// ---------------------------------------------------------------------------
// kRow: C[row0..+128][64] = round_tf32( X @ Wpre + bias )
// ---------------------------------------------------------------------------
__global__ void __launch_bounds__(256, 3)
kRow(const float* __restrict__ X, const float* __restrict__ Wpre,
     const float* __restrict__ bias, float* __restrict__ out) {
    extern __shared__ float sm[];
    float* Wt = sm;
    float* bs = Wt + HD * PW;
    float* Xs = bs + HD;

    const int tid = threadIdx.x;
    const int lane = tid & 31, w = tid >> 5;
    const int g = lane >> 2, t = lane & 3;
    const int wm = w & 3, wn = w >> 2;           // 4 x 2 warp grid
    const long row0 = (long)blockIdx.x * 128;

    #pragma unroll
    for (int i = 0; i < 8; i++) {
        int idx = tid + i * 256;
        int r = idx >> 4, c4 = (idx & 15) << 2;
        cpa16(Xs + r * PC + c4, X + (row0 + r) * 64 + c4);
    }
    #pragma unroll
    for (int i = 0; i < 4; i++) {
        int idx = tid + i * 256;
        int r = idx >> 4, c4 = (idx & 15) << 2;
        cpa16(Wt + r * PW + c4, Wpre + r * 64 + c4);
    }
    asm volatile("cp.async.commit_group;\n");
    if (tid < HD) bs[tid] = bias[tid];
    asm volatile("cp.async.wait_group 0;\n");
    __syncthreads();

    float acc[2][4][4];
    #pragma unroll
    for (int i = 0; i < 2; i++)
        #pragma unroll
        for (int j = 0; j < 4; j++)
            #pragma unroll
            for (int r = 0; r < 4; r++) acc[i][j][r] = 0.f;

    #pragma unroll
    for (int k0 = 0; k0 < 64; k0 += 8) {
        uint32_t a[2][4];
        #pragma unroll
        for (int i = 0; i < 2; i++) {
            const float* ap = Xs + (wm * 32 + i * 16 + g) * PC + k0 + t;
            a[i][0] = f2tf(ap[0]);
            a[i][1] = f2tf(ap[8 * PC]);
            a[i][2] = f2tf(ap[4]);
            a[i][3] = f2tf(ap[8 * PC + 4]);
        }
        #pragma unroll
        for (int j = 0; j < 4; j++) {
            uint32_t b0 = __float_as_uint(Wt[(k0 + t) * PW + wn * 32 + j * 8 + g]);
            uint32_t b1 = __float_as_uint(Wt[(k0 + t + 4) * PW + wn * 32 + j * 8 + g]);
            mma8(acc[0][j], a[0], b0, b1);
            mma8(acc[1][j], a[1], b0, b1);
        }
    }

    #pragma unroll
    for (int i = 0; i < 2; i++)
        #pragma unroll
        for (int j = 0; j < 4; j++)
            #pragma unroll
            for (int r = 0; r < 4; r++) {
                int row = wm * 32 + i * 16 + g + ((r >> 1) << 3);
                int col = wn * 32 + j * 8 + 2 * t + (r & 1);
                float v = acc[i][j][r] + bs[col];
                out[(row0 + row) * 64 + col] = __uint_as_float(f2tf(v));
            }
}

// ---------------------------------------------------------------------------
// kAdj: T = relu(adj_tile @ S / 100); U = T @ Wpre + bias; store (masked fp32
// or tf32-rounded). Single-sync double-buffered cp.async pipeline.
// ---------------------------------------------------------------------------
template <int MASKED>
__global__ void __launch_bounds__(256, 3)
kAdj(const float* __restrict__ adj, const float* __restrict__ S,
     const float* __restrict__ Wpre, const float* __restrict__ bias,
     const float* __restrict__ nmask, float* __restrict__ out) {
    extern __shared__ float sm[];
    float* Wt   = sm;                  // 64 x PW (prepped tf32)
    float* bs   = Wt + HD * PW;        // 64
    float* Bs   = bs + HD;             // 2 x KT x PW
    float* adjs = Bs + 2 * KT * PW;    // 2 x 128 x PADJ
    float* Csm  = adjs;                // reused after mainloop (128 x PC)

    const int tid = threadIdx.x;
    const int lane = tid & 31, w = tid >> 5;
    const int g = lane >> 2, t = lane & 3;
    const int wm = w & 3, wn = w >> 2;           // 4 x 2 warp grid
    const int b = blockIdx.y;
    const int row0 = blockIdx.x * 128;

    const float* adjb = adj + ((size_t)b * NP + row0) * NP;
    const float* Sb   = S + (size_t)b * NP * HD;

    auto prefetch = [&](int c, int buf) {
        float* ad = adjs + buf * 128 * PADJ;
        #pragma unroll
        for (int i = 0; i < 4; i++) {
            int idx = tid + i * 256;
            int r = idx >> 3, s4 = (idx & 7) << 2;
            cpa16(ad + r * PADJ + s4, adjb + (size_t)r * NP + c * KT + s4);
        }
        float* bd = Bs + buf * KT * PW;
        #pragma unroll
        for (int i = 0; i < 2; i++) {
            int idx = tid + i * 256;
            int r = idx >> 4, s4 = (idx & 15) << 2;
            cpa16(bd + r * PW + s4, Sb + (size_t)(c * KT + r) * HD + s4);
        }
        asm volatile("cp.async.commit_group;\n");
    };

    // chunk 0 + weight tile in the first group
    {
        float* ad = adjs;
        #pragma unroll
        for (int i = 0; i < 4; i++) {
            int idx = tid + i * 256;
            int r = idx >> 3, s4 = (idx & 7) << 2;
            cpa16(ad + r * PADJ + s4, adjb + (size_t)r * NP + s4);
        }
        #pragma unroll
        for (int i = 0; i < 2; i++) {
            int idx = tid + i * 256;
            int r = idx >> 4, s4 = (idx & 15) << 2;
            cpa16(Bs + r * PW + s4, Sb + (size_t)r * HD + s4);
        }
        #pragma unroll
        for (int i = 0; i < 4; i++) {
            int idx = tid + i * 256;
            int r = idx >> 4, c4 = (idx & 15) << 2;
            cpa16(Wt + r * PW + c4, Wpre + r * 64 + c4);
        }
        asm volatile("cp.async.commit_group;\n");
    }
    if (tid < HD) bs[tid] = bias[tid];

    float acc[2][4][4];
    #pragma unroll
    for (int i = 0; i < 2; i++)
        #pragma unroll
        for (int j = 0; j < 4; j++)
            #pragma unroll
            for (int r = 0; r < 4; r++) acc[i][j][r] = 0.f;

    const int NCH = NP / KT;   // 8
    for (int c = 0; c < NCH; c++) {
        int buf = c & 1;
        asm volatile("cp.async.wait_group 0;\n");   // chunk c resident
        __syncthreads();                            // all warps past chunk c-1
        if (c + 1 < NCH) prefetch(c + 1, buf ^ 1);  // overlaps compute below

        const float* At = adjs + buf * 128 * PADJ;
        const float* Bt = Bs + buf * KT * PW;
        #pragma unroll
        for (int kk = 0; kk < KT; kk += 8) {
            uint32_t a[2][4];
            #pragma unroll
            for (int i = 0; i < 2; i++) {
                const float* ap = At + (wm * 32 + i * 16 + g) * PADJ + kk + t;
                a[i][0] = f2tf(ap[0]);
                a[i][1] = f2tf(ap[8 * PADJ]);
                a[i][2] = f2tf(ap[4]);
                a[i][3] = f2tf(ap[8 * PADJ + 4]);
            }
            #pragma unroll
            for (int j = 0; j < 4; j++) {
                uint32_t b0 = __float_as_uint(Bt[(kk + t) * PW + wn * 32 + j * 8 + g]);
                uint32_t b1 = __float_as_uint(Bt[(kk + t + 4) * PW + wn * 32 + j * 8 + g]);
                mma8(acc[0][j], a[0], b0, b1);
                mma8(acc[1][j], a[1], b0, b1);
            }
        }
    }

    __syncthreads();   // all reads of adjs done before reuse as Csm

    // T = round(relu(acc/100)) -> Csm
    #pragma unroll
    for (int i = 0; i < 2; i++)
        #pragma unroll
        for (int j = 0; j < 4; j++)
            #pragma unroll
            for (int r = 0; r < 4; r++) {
                int row = wm * 32 + i * 16 + g + ((r >> 1) << 3);
                int col = wn * 32 + j * 8 + 2 * t + (r & 1);
                float v = fmaxf(acc[i][j][r] * 0.01f, 0.f);
                Csm[row * PC + col] = __uint_as_float(f2tf(v));
            }
    __syncthreads();

    // U = T @ Wz
    #pragma unroll
    for (int i = 0; i < 2; i++)
        #pragma unroll
        for (int j = 0; j < 4; j++)
            #pragma unroll
            for (int r = 0; r < 4; r++) acc[i][j][r] = 0.f;

    #pragma unroll
    for (int k0 = 0; k0 < 64; k0 += 8) {
        uint32_t a[2][4];
        #pragma unroll
        for (int i = 0; i < 2; i++) {
            const float* ap = Csm + (wm * 32 + i * 16 + g) * PC + k0 + t;
            a[i][0] = __float_as_uint(ap[0]);
            a[i][1] = __float_as_uint(ap[8 * PC]);
            a[i][2] = __float_as_uint(ap[4]);
            a[i][3] = __float_as_uint(ap[8 * PC + 4]);
        }
        #pragma unroll
        for (int j = 0; j < 4; j++) {
            uint32_t b0 = __float_as_uint(Wt[(k0 + t) * PW + wn * 32 + j * 8 + g]);
            uint32_t b1 = __float_as_uint(Wt[(k0 + t + 4) * PW + wn * 32 + j * 8 + g]);
            mma8(acc[0][j], a[0], b0, b1);
            mma8(acc[1][j], a[1], b0, b1);
        }
    }

    float mv[2][2] = {{1.f, 1.f}, {1.f, 1.f}};
    if (MASKED) {
        const float* mrowp = nmask + (size_t)b * NP + row0;
        #pragma unroll
        for (int i = 0; i < 2; i++) {
            mv[i][0] = mrowp[wm * 32 + i * 16 + g];
            mv[i][1] = mrowp[wm * 32 + i * 16 + g + 8];
        }
    }
    float* outb = out + ((size_t)b * NP + row0) * HD;
    #pragma unroll
    for (int i = 0; i < 2; i++)
        #pragma unroll
        for (int j = 0; j < 4; j++)
            #pragma unroll
            for (int r = 0; r < 4; r++) {
                int row = wm * 32 + i * 16 + g + ((r >> 1) << 3);
                int col = wn * 32 + j * 8 + 2 * t + (r & 1);
                float v = acc[i][j][r] + bs[col];
                if (MASKED) {
                    v *= mv[i][r >> 1];
                    outb[(size_t)row * HD + col] = v;
                } else {
                    outb[(size_t)row * HD + col] = __uint_as_float(f2tf(v));
                }
            }
}

// ---------------------------------------------------------------------------
extern "C" void kernel_launch(void* const* d_in, const int* in_sizes, int n_in,
                              void* d_out, int out_size) {
    const float* x       = (const float*)d_in[0];
    const float* adj     = (const float*)d_in[1];
    const float* nmask   = (const float*)d_in[2];
    const float* W_embed = (const float*)d_in[3];
    const float* W0      = (const float*)d_in[4];
    const float* b0      = (const float*)d_in[5];
    const float* W1      = (const float*)d_in[6];
    const float* b1      = (const float*)d_in[7];
    const float* W_out   = (const float*)d_in[8];
    const float* b_out   = (const float*)d_in[9];
    float* out = (float*)d_out;

    float *bufA = nullptr, *bufB = nullptr, *wpre = nullptr;
    cudaGetSymbolAddress((void**)&bufA, g_bufA);
    cudaGetSymbolAddress((void**)&bufB, g_bufB);
    cudaGetSymbolAddress((void**)&wpre, g_Wpre);

    cudaFuncSetAttribute(kRow, cudaFuncAttributeMaxDynamicSharedMemorySize,
                         (int)SMEM_ROW);
    cudaFuncSetAttribute(kAdj<0>, cudaFuncAttributeMaxDynamicSharedMemorySize,
                         (int)SMEM_ADJ);
    cudaFuncSetAttribute(kAdj<1>, cudaFuncAttributeMaxDynamicSharedMemorySize,
                         (int)SMEM_ADJ);

    kPrep<<<48, 256>>>(W_embed, W0, W1, W_out, wpre);
    kRow<<<1024, 256, SMEM_ROW>>>(x, wpre, b0, bufA);
    kAdj<0><<<dim3(2, 512), 256, SMEM_ADJ>>>(adj, bufA, wpre + 4096, b1,
                                             nullptr, bufB);
    kAdj<1><<<dim3(2, 512), 256, SMEM_ADJ>>>(adj, bufB, wpre + 8192, b_out,
                                             nmask, out);
}

// round 6
// speedup vs baseline: 2.2472x; 1.0345x over previous
#include <cuda_runtime.h>
#include <cstdint>

// HGCN (math-reduced) as 3 GEMM kernels + weight-prep:
//   prep: W01 = tf32(We @ W0z), W1z/Woz = tf32(row0-zeroed W1/W_out)
//   s0  = x @ W01 + b0                              (kRow)
//   s1  = relu(adj@s0/100) @ W1z + b1               (kAdj<0>)
//   out = (relu(adj@s1/100) @ Woz + b_out) * mask   (kAdj<1>)
// kAdj: CTA = full 256x64 batch tile, warp tile m64n32 (4Mx2N warps),
// triple-buffered KT=16 cp.async pipeline (prefetch distance 2).

static constexpr int NP   = 256;
static constexpr int HD   = 64;
static constexpr int PW   = 72;  // B pitch: t*8+g pattern conflict-free
static constexpr int PADJ = 20;  // A pitch: g*20+t covers all banks (gcd(20,32)=4, x4 lanes)
static constexpr int PC   = 68;  // epilogue A pitch: 4g+t conflict-free
static constexpr int KT   = 16;
static constexpr int NST  = 3;   // pipeline stages
static constexpr int NCH  = NP / KT;   // 16

__device__ float g_bufA[131072 * 64];
__device__ float g_bufB[131072 * 64];
__device__ float g_Wpre[3 * 64 * 64];   // [0]=W01, [1]=W1z, [2]=Woz (tf32)

// smem floats: Wt 64*72, bias 64, Bs 3*16*72, adjs 3*256*20
static constexpr int SM_WT   = 0;
static constexpr int SM_BS   = SM_WT + HD * PW;        // bias
static constexpr int SM_B    = SM_BS + HD;             // Bs tiles
static constexpr int SM_ADJ  = SM_B + NST * KT * PW;   // adj tiles
static constexpr int SM_TOT  = SM_ADJ + NST * NP * PADJ;
static constexpr size_t SMEM_ADJ = SM_TOT * sizeof(float);
// Csm (256 x PC = 17408 floats) overlays Bs+adjs (18816 floats)
static constexpr size_t SMEM_ROW = (HD * PW + HD + 128 * PC) * 4;

__device__ __forceinline__ uint32_t f2tf(float f) {
    uint32_t u;
    asm("cvt.rna.tf32.f32 %0, %1;" : "=r"(u) : "f"(f));
    return u;
}

__device__ __forceinline__ void mma8(float* c, const uint32_t* a,
                                     uint32_t b0, uint32_t b1) {
    asm volatile(
        "mma.sync.aligned.m16n8k8.row.col.f32.tf32.tf32.f32 "
        "{%0,%1,%2,%3}, {%4,%5,%6,%7}, {%8,%9}, {%0,%1,%2,%3};\n"
        : "+f"(c[0]), "+f"(c[1]), "+f"(c[2]), "+f"(c[3])
        : "r"(a[0]), "r"(a[1]), "r"(a[2]), "r"(a[3]), "r"(b0), "r"(b1));
}

__device__ __forceinline__ void cpa16(float* dst, const float* src) {
    uint32_t d = (uint32_t)__cvta_generic_to_shared(dst);
    asm volatile("cp.async.ca.shared.global [%0], [%1], 16;\n" :: "r"(d), "l"(src));
}

// ---------------------------------------------------------------------------
__global__ void __launch_bounds__(256)
kPrep(const float* __restrict__ We, const float* __restrict__ W0,
      const float* __restrict__ W1, const float* __restrict__ Wo,
      float* __restrict__ Wpre) {
    int id = blockIdx.x * 256 + threadIdx.x;
    int which = id >> 12;
    int li = id & 4095;
    int r = li >> 6, c = li & 63;
    float v;
    if (which == 0) {
        float s = 0.f;
        #pragma unroll 8
        for (int k = 1; k < 64; k++) s += We[r * 64 + k] * W0[k * 64 + c];
        v = s;
    } else {
        const float* W = (which == 1) ? W1 : Wo;
        v = (r == 0) ? 0.f : W[li];
    }
    Wpre[id] = __uint_as_float(f2tf(v));
}

// ---------------------------------------------------------------------------
// kRow: C[row0..+128][64] = round_tf32( X @ Wpre + bias )
// ---------------------------------------------------------------------------
__global__ void __launch_bounds__(256, 3)
kRow(const float* __restrict__ X, const float* __restrict__ Wpre,
     const float* __restrict__ bias, float* __restrict__ out) {
    extern __shared__ float sm[];
    float* Wt = sm;
    float* bs = Wt + HD * PW;
    float* Xs = bs + HD;

    const int tid = threadIdx.x;
    const int lane = tid & 31, w = tid >> 5;
    const int g = lane >> 2, t = lane & 3;
    const int wm = w & 3, wn = w >> 2;
    const long row0 = (long)blockIdx.x * 128;

    #pragma unroll
    for (int i = 0; i < 8; i++) {
        int idx = tid + i * 256;
        int r = idx >> 4, c4 = (idx & 15) << 2;
        cpa16(Xs + r * PC + c4, X + (row0 + r) * 64 + c4);
    }
    #pragma unroll
    for (int i = 0; i < 4; i++) {
        int idx = tid + i * 256;
        int r = idx >> 4, c4 = (idx & 15) << 2;
        cpa16(Wt + r * PW + c4, Wpre + r * 64 + c4);
    }
    asm volatile("cp.async.commit_group;\n");
    if (tid < HD) bs[tid] = bias[tid];
    asm volatile("cp.async.wait_group 0;\n");
    __syncthreads();

    float acc[2][4][4];
    #pragma unroll
    for (int i = 0; i < 2; i++)
        #pragma unroll
        for (int j = 0; j < 4; j++)
            #pragma unroll
            for (int r = 0; r < 4; r++) acc[i][j][r] = 0.f;

    #pragma unroll
    for (int k0 = 0; k0 < 64; k0 += 8) {
        uint32_t a[2][4];
        #pragma unroll
        for (int i = 0; i < 2; i++) {
            const float* ap = Xs + (wm * 32 + i * 16 + g) * PC + k0 + t;
            a[i][0] = f2tf(ap[0]);
            a[i][1] = f2tf(ap[8 * PC]);
            a[i][2] = f2tf(ap[4]);
            a[i][3] = f2tf(ap[8 * PC + 4]);
        }
        #pragma unroll
        for (int j = 0; j < 4; j++) {
            uint32_t b0 = __float_as_uint(Wt[(k0 + t) * PW + wn * 32 + j * 8 + g]);
            uint32_t b1 = __float_as_uint(Wt[(k0 + t + 4) * PW + wn * 32 + j * 8 + g]);
            mma8(acc[0][j], a[0], b0, b1);
            mma8(acc[1][j], a[1], b0, b1);
        }
    }

    #pragma unroll
    for (int i = 0; i < 2; i++)
        #pragma unroll
        for (int j = 0; j < 4; j++)
            #pragma unroll
            for (int r = 0; r < 4; r++) {
                int row = wm * 32 + i * 16 + g + ((r >> 1) << 3);
                int col = wn * 32 + j * 8 + 2 * t + (r & 1);
                float v = acc[i][j][r] + bs[col];
                out[(row0 + row) * 64 + col] = __uint_as_float(f2tf(v));
            }
}

// ---------------------------------------------------------------------------
// kAdj: one CTA per batch. T = relu(adj_b @ S_b / 100); U = T @ Wpre + bias.
// ---------------------------------------------------------------------------
template <int MASKED>
__global__ void __launch_bounds__(256, 2)
kAdj(const float* __restrict__ adj, const float* __restrict__ S,
     const float* __restrict__ Wpre, const float* __restrict__ bias,
     const float* __restrict__ nmask, float* __restrict__ out) {
    extern __shared__ float sm[];
    float* Wt   = sm + SM_WT;
    float* bs   = sm + SM_BS;
    float* Bst  = sm + SM_B;
    float* adjs = sm + SM_ADJ;
    float* Csm  = sm + SM_B;     // overlays Bs+adjs after mainloop

    const int tid = threadIdx.x;
    const int lane = tid & 31, w = tid >> 5;
    const int g = lane >> 2, t = lane & 3;
    const int wm = w & 3, wn = w >> 2;          // 4 x 2 warp grid, m64 x n32
    const int b = blockIdx.x;

    const float* adjb = adj + (size_t)b * NP * NP;
    const float* Sb   = S + (size_t)b * NP * HD;

    auto prefetch = [&](int c, bool withW) {
        int buf = c % NST;
        float* ad = adjs + buf * NP * PADJ;
        #pragma unroll
        for (int i = 0; i < 4; i++) {
            int idx = tid + i * 256;
            int r = idx >> 2, s4 = (idx & 3) << 2;
            cpa16(ad + r * PADJ + s4, adjb + (size_t)r * NP + c * KT + s4);
        }
        float* bd = Bst + buf * KT * PW;
        {
            int r = tid >> 4, s4 = (tid & 15) << 2;
            cpa16(bd + r * PW + s4, Sb + (size_t)(c * KT + r) * HD + s4);
        }
        if (withW) {
            #pragma unroll
            for (int i = 0; i < 4; i++) {
                int idx = tid + i * 256;
                int r = idx >> 4, c4 = (idx & 15) << 2;
                cpa16(Wt + r * PW + c4, Wpre + r * 64 + c4);
            }
        }
        asm volatile("cp.async.commit_group;\n");
    };

    prefetch(0, true);
    prefetch(1, false);
    if (tid < HD) bs[tid] = bias[tid];

    float acc[4][4][4];
    #pragma unroll
    for (int i = 0; i < 4; i++)
        #pragma unroll
        for (int j = 0; j < 4; j++)
            #pragma unroll
            for (int r = 0; r < 4; r++) acc[i][j][r] = 0.f;

    for (int c = 0; c < NCH; c++) {
        if (c < NCH - 2) asm volatile("cp.async.wait_group 1;\n");
        else             asm volatile("cp.async.wait_group 0;\n");
        __syncthreads();                       // chunk c resident; c-1 reads done
        if (c + 2 < NCH) prefetch(c + 2, false);   // buffer (c+2)%3 free

        const float* At = adjs + (c % NST) * NP * PADJ;
        const float* Bt = Bst + (c % NST) * KT * PW;
        #pragma unroll
        for (int kk = 0; kk < KT; kk += 8) {
            uint32_t a[4][4];
            #pragma unroll
            for (int i = 0; i < 4; i++) {
                const float* ap = At + (wm * 64 + i * 16 + g) * PADJ + kk + t;
                a[i][0] = f2tf(ap[0]);
                a[i][1] = f2tf(ap[8 * PADJ]);
                a[i][2] = f2tf(ap[4]);
                a[i][3] = f2tf(ap[8 * PADJ + 4]);
            }
            #pragma unroll
            for (int j = 0; j < 4; j++) {
                uint32_t b0 = __float_as_uint(Bt[(kk + t) * PW + wn * 32 + j * 8 + g]);
                uint32_t b1 = __float_as_uint(Bt[(kk + t + 4) * PW + wn * 32 + j * 8 + g]);
                #pragma unroll
                for (int i = 0; i < 4; i++) mma8(acc[i][j], a[i], b0, b1);
            }
        }
    }

    __syncthreads();   // all mainloop smem reads done before Csm overlay

    // T = round_tf32(relu(acc/100)) -> Csm (float2 stores, cols 2t,2t+1)
    #pragma unroll
    for (int i = 0; i < 4; i++)
        #pragma unroll
        for (int j = 0; j < 4; j++)
            #pragma unroll
            for (int h = 0; h < 2; h++) {
                int row = wm * 64 + i * 16 + g + h * 8;
                int col = wn * 32 + j * 8 + 2 * t;
                float2 v;
                v.x = __uint_as_float(f2tf(fmaxf(acc[i][j][2 * h]     * 0.01f, 0.f)));
                v.y = __uint_as_float(f2tf(fmaxf(acc[i][j][2 * h + 1] * 0.01f, 0.f)));
                *reinterpret_cast<float2*>(&Csm[row * PC + col]) = v;
            }
    __syncthreads();

    // U = T @ Wz
    #pragma unroll
    for (int i = 0; i < 4; i++)
        #pragma unroll
        for (int j = 0; j < 4; j++)
            #pragma unroll
            for (int r = 0; r < 4; r++) acc[i][j][r] = 0.f;

    #pragma unroll
    for (int k0 = 0; k0 < 64; k0 += 8) {
        uint32_t a[4][4];
        #pragma unroll
        for (int i = 0; i < 4; i++) {
            const float* ap = Csm + (wm * 64 + i * 16 + g) * PC + k0 + t;
            a[i][0] = __float_as_uint(ap[0]);
            a[i][1] = __float_as_uint(ap[8 * PC]);
            a[i][2] = __float_as_uint(ap[4]);
            a[i][3] = __float_as_uint(ap[8 * PC + 4]);
        }
        #pragma unroll
        for (int j = 0; j < 4; j++) {
            uint32_t b0 = __float_as_uint(Wt[(k0 + t) * PW + wn * 32 + j * 8 + g]);
            uint32_t b1 = __float_as_uint(Wt[(k0 + t + 4) * PW + wn * 32 + j * 8 + g]);
            #pragma unroll
            for (int i = 0; i < 4; i++) mma8(acc[i][j], a[i], b0, b1);
        }
    }

    float mv[4][2];
    #pragma unroll
    for (int i = 0; i < 4; i++) { mv[i][0] = 1.f; mv[i][1] = 1.f; }
    if (MASKED) {
        const float* mrowp = nmask + (size_t)b * NP;
        #pragma unroll
        for (int i = 0; i < 4; i++) {
            mv[i][0] = mrowp[wm * 64 + i * 16 + g];
            mv[i][1] = mrowp[wm * 64 + i * 16 + g + 8];
        }
    }
    float* outb = out + (size_t)b * NP * HD;
    #pragma unroll
    for (int i = 0; i < 4; i++)
        #pragma unroll
        for (int j = 0; j < 4; j++)
            #pragma unroll
            for (int h = 0; h < 2; h++) {
                int row = wm * 64 + i * 16 + g + h * 8;
                int col = wn * 32 + j * 8 + 2 * t;
                float v0 = acc[i][j][2 * h]     + bs[col];
                float v1 = acc[i][j][2 * h + 1] + bs[col + 1];
                float2 v;
                if (MASKED) {
                    v.x = v0 * mv[i][h];
                    v.y = v1 * mv[i][h];
                } else {
                    v.x = __uint_as_float(f2tf(v0));
                    v.y = __uint_as_float(f2tf(v1));
                }
                *reinterpret_cast<float2*>(&outb[(size_t)row * HD + col]) = v;
            }
}

// ---------------------------------------------------------------------------
extern "C" void kernel_launch(void* const* d_in, const int* in_sizes, int n_in,
                              void* d_out, int out_size) {
    const float* x       = (const float*)d_in[0];
    const float* adj     = (const float*)d_in[1];
    const float* nmask   = (const float*)d_in[2];
    const float* W_embed = (const float*)d_in[3];
    const float* W0      = (const float*)d_in[4];
    const float* b0      = (const float*)d_in[5];
    const float* W1      = (const float*)d_in[6];
    const float* b1      = (const float*)d_in[7];
    const float* W_out   = (const float*)d_in[8];
    const float* b_out   = (const float*)d_in[9];
    float* out = (float*)d_out;

    float *bufA = nullptr, *bufB = nullptr, *wpre = nullptr;
    cudaGetSymbolAddress((void**)&bufA, g_bufA);
    cudaGetSymbolAddress((void**)&bufB, g_bufB);
    cudaGetSymbolAddress((void**)&wpre, g_Wpre);

    cudaFuncSetAttribute(kRow, cudaFuncAttributeMaxDynamicSharedMemorySize,
                         (int)SMEM_ROW);
    cudaFuncSetAttribute(kAdj<0>, cudaFuncAttributeMaxDynamicSharedMemorySize,
                         (int)SMEM_ADJ);
    cudaFuncSetAttribute(kAdj<1>, cudaFuncAttributeMaxDynamicSharedMemorySize,
                         (int)SMEM_ADJ);

    kPrep<<<48, 256>>>(W_embed, W0, W1, W_out, wpre);
    kRow<<<1024, 256, SMEM_ROW>>>(x, wpre, b0, bufA);
    kAdj<0><<<512, 256, SMEM_ADJ>>>(adj, bufA, wpre + 4096, b1, nullptr, bufB);
    kAdj<1><<<512, 256, SMEM_ADJ>>>(adj, bufB, wpre + 8192, b_out, nmask, out);
}

// round 9
// speedup vs baseline: 2.8856x; 1.2841x over previous
#include <cuda_runtime.h>
#include <cuda_fp16.h>
#include <cstdint>

// HGCN (math-reduced), fp16-operand mma.sync edition (tcgen05 unavailable:
// harness ptxas targets sm_100 without 'a'):
//   prep: W01h = half(We @ W0z), W1zh/Wozh = half(row0-zeroed W1/W_out), [k][n]
//   s0  = x @ W01 + b0                     (kRowH, -> half S, row-major)
//   s1  = relu(adj@s0/100) @ W1z + b1      (kAdjH<0>)
//   out = (relu(adj@s1/100) @ Woz + b_out) * mask   (kAdjH<1>)
// fp16 m16n8k16 mma with fp32 accum; A via ldmatrix.x4, B via ldmatrix.x4.trans.

static constexpr int NP = 256, HD = 64;

__device__ __half   g_bufA[131072 * 64];    // S buffers, row-major half
__device__ __half   g_bufB[131072 * 64];
__device__ uint16_t g_WpreH[3 * 4096];      // [0]=W01h, [1]=W1zh, [2]=Wozh  ([k][n])

// ---- kAdjH smem byte offsets ----------------------------------------------
static constexpr int AJ_ST0  = 0;        // adj fp32 stage, 256x16 f32 = 16KB
static constexpr int AJ_ST1  = 16384;
static constexpr int AJ_AH0  = 32768;    // adj half tile, 256 rows x 48B
static constexpr int AJ_AH1  = 45056;
static constexpr int AJ_BH0  = 57344;    // S chunk, 16 rows x 144B
static constexpr int AJ_BH1  = 59648;
static constexpr int AJ_W    = 61952;    // W half, 64 rows x 144B
static constexpr int AJ_BIAS = 71168;    // 64 f32
static constexpr int AJ_BYTES= 71424;    // ~69.8KB -> 2 CTA/SM
static constexpr int AJ_T    = 0;        // T tile overlays stages: 256x144B=36864
// ---- kRowH smem -----------------------------------------------------------
static constexpr int KR_ST   = 0;        // x stage 128x64 f32 = 32KB
static constexpr int KR_XH   = 32768;    // x half 128 rows x 144B
static constexpr int KR_W    = 51200;
static constexpr int KR_BIAS = 60416;
static constexpr int KR_BYTES= 60672;

// ---- helpers ---------------------------------------------------------------
__device__ __forceinline__ uint32_t smem_u32(const void* p) {
    uint32_t a;
    asm("{ .reg .u64 t; cvta.to.shared.u64 t, %1; cvt.u32.u64 %0, t; }"
        : "=r"(a) : "l"(p));
    return a;
}
__device__ __forceinline__ void cpa16(uint32_t dst, const void* src) {
    asm volatile("cp.async.ca.shared.global [%0], [%1], 16;\n"
                 :: "r"(dst), "l"(src));
}
__device__ __forceinline__ void ldsm4(uint32_t* r, uint32_t addr) {
    asm volatile("ldmatrix.sync.aligned.m8n8.x4.shared.b16 {%0,%1,%2,%3}, [%4];"
                 : "=r"(r[0]), "=r"(r[1]), "=r"(r[2]), "=r"(r[3]) : "r"(addr));
}
__device__ __forceinline__ void ldsm4t(uint32_t* r, uint32_t addr) {
    asm volatile("ldmatrix.sync.aligned.m8n8.x4.trans.shared.b16 {%0,%1,%2,%3}, [%4];"
                 : "=r"(r[0]), "=r"(r[1]), "=r"(r[2]), "=r"(r[3]) : "r"(addr));
}
__device__ __forceinline__ void mma16(float* c, const uint32_t* a,
                                      uint32_t b0, uint32_t b1) {
    asm volatile(
        "mma.sync.aligned.m16n8k16.row.col.f32.f16.f16.f32 "
        "{%0,%1,%2,%3}, {%4,%5,%6,%7}, {%8,%9}, {%0,%1,%2,%3};\n"
        : "+f"(c[0]), "+f"(c[1]), "+f"(c[2]), "+f"(c[3])
        : "r"(a[0]), "r"(a[1]), "r"(a[2]), "r"(a[3]), "r"(b0), "r"(b1));
}
__device__ __forceinline__ uint32_t pk2h(float a, float b) {
    __half2 h = __floats2half2_rn(a, b);
    return *reinterpret_cast<uint32_t*>(&h);
}

// ---------------------------------------------------------------------------
// kPrep: [0]: W01h[k*64+n] = half((We @ W0z)[k][n]);
//        [1]/[2]: half(W1/W_out with row k=0 zeroed), [k][n] row-major.
// ---------------------------------------------------------------------------
__global__ void __launch_bounds__(256)
kPrep(const float* __restrict__ We, const float* __restrict__ W0,
      const float* __restrict__ W1, const float* __restrict__ Wo,
      uint16_t* __restrict__ WpreH) {
    int id = blockIdx.x * 256 + threadIdx.x;      // 48 blocks
    int which = id >> 12;
    int li = id & 4095;
    int k = li >> 6, n = li & 63;
    float v;
    if (which == 0) {
        float s = 0.f;
        #pragma unroll 8
        for (int kk = 1; kk < 64; kk++) s += We[k * 64 + kk] * W0[kk * 64 + n];
        v = s;
    } else {
        const float* W = (which == 1) ? W1 : Wo;
        v = (k == 0) ? 0.f : W[li];
    }
    __half h = __float2half_rn(v);
    WpreH[id] = *reinterpret_cast<uint16_t*>(&h);
}

// ---------------------------------------------------------------------------
// kRowH: S = half(x @ W01 + b0), row-major. 128 rows/CTA, grid 1024.
// ---------------------------------------------------------------------------
__global__ void __launch_bounds__(256, 2)
kRowH(const float* __restrict__ X, const uint16_t* __restrict__ Wh,
      const float* __restrict__ bias, __half* __restrict__ S) {
    extern __shared__ char sm[];
    const uint32_t sb = smem_u32(sm);
    const int tid = threadIdx.x;
    const int lane = tid & 31, w = tid >> 5;
    const int g = lane >> 2, t = lane & 3;
    const int wm = w & 3, wn = w >> 2;            // 4m x 2n; warp m32 x n32
    const long row0 = (long)blockIdx.x * 128;

    // stage x (2048 units) + W (512 units)
    #pragma unroll
    for (int i = 0; i < 8; i++) {
        int u = tid + i * 256;
        cpa16(sb + KR_ST + u * 16, X + (row0 + (u >> 4)) * 64 + (u & 15) * 4);
    }
    #pragma unroll
    for (int i = 0; i < 2; i++) {
        int u = tid + i * 256;
        cpa16(sb + KR_W + (u >> 3) * 144 + (u & 7) * 16, Wh + (u >> 3) * 64 + (u & 7) * 8);
    }
    asm volatile("cp.async.commit_group;\n");
    if (tid < HD) *reinterpret_cast<float*>(sm + KR_BIAS + tid * 4) = bias[tid];
    asm volatile("cp.async.wait_group 0;\n");
    __syncthreads();

    // convert x -> half (pitch 144B rows)
    #pragma unroll
    for (int i = 0; i < 8; i++) {
        int u = tid + i * 256;
        int r = u >> 4, q = u & 15;
        float4 v = *reinterpret_cast<float4*>(sm + KR_ST + u * 16);
        uint2 h;
        h.x = pk2h(v.x, v.y);
        h.y = pk2h(v.z, v.w);
        *reinterpret_cast<uint2*>(sm + KR_XH + r * 144 + q * 8) = h;
    }
    __syncthreads();

    float acc[2][4][4];
    #pragma unroll
    for (int i = 0; i < 2; i++)
        #pragma unroll
        for (int j = 0; j < 4; j++)
            #pragma unroll
            for (int r = 0; r < 4; r++) acc[i][j][r] = 0.f;

    #pragma unroll
    for (int ks = 0; ks < 4; ks++) {              // K = 64 = 4 x k16
        uint32_t a[2][4], bb[2][4];
        #pragma unroll
        for (int i = 0; i < 2; i++)
            ldsm4(a[i], sb + KR_XH + (wm * 32 + i * 16 + (lane & 15)) * 144
                        + ks * 32 + (lane >> 4) * 16);
        #pragma unroll
        for (int p = 0; p < 2; p++)
            ldsm4t(bb[p], sb + KR_W + (ks * 16 + (lane & 15)) * 144
                          + (wn * 32 + p * 16 + (lane >> 4) * 8) * 2);
        #pragma unroll
        for (int j = 0; j < 4; j++) {
            uint32_t b0 = bb[j >> 1][(j & 1) * 2];
            uint32_t b1 = bb[j >> 1][(j & 1) * 2 + 1];
            mma16(acc[0][j], a[0], b0, b1);
            mma16(acc[1][j], a[1], b0, b1);
        }
    }

    const float* bsm = reinterpret_cast<const float*>(sm + KR_BIAS);
    #pragma unroll
    for (int i = 0; i < 2; i++)
        #pragma unroll
        for (int j = 0; j < 4; j++) {
            int col = wn * 32 + j * 8 + 2 * t;
            float b0 = bsm[col], b1 = bsm[col + 1];
            int r0 = wm * 32 + i * 16 + g;
            uint32_t h0 = pk2h(acc[i][j][0] + b0, acc[i][j][1] + b1);
            uint32_t h1 = pk2h(acc[i][j][2] + b0, acc[i][j][3] + b1);
            *reinterpret_cast<uint32_t*>(S + (row0 + r0) * 64 + col)     = h0;
            *reinterpret_cast<uint32_t*>(S + (row0 + r0 + 8) * 64 + col) = h1;
        }
}

// ---------------------------------------------------------------------------
// kAdjH: one CTA per batch. D = adj_h @ S_h (fp32 accum, 16 k16 chunks);
// T = half(relu(D/100)); U = T @ Wz + bias.
// MASKED=0: S_out = half(U) row-major; MASKED=1: out = fp32 U * mask.
// ---------------------------------------------------------------------------
template <int MASKED>
__global__ void __launch_bounds__(256, 2)
kAdjH(const float* __restrict__ adj, const __half* __restrict__ S,
      const uint16_t* __restrict__ Wh, const float* __restrict__ bias,
      const float* __restrict__ nmask, float* __restrict__ outf,
      __half* __restrict__ outh) {
    extern __shared__ char sm[];
    const uint32_t sb = smem_u32(sm);
    const int tid = threadIdx.x;
    const int lane = tid & 31, w = tid >> 5;
    const int g = lane >> 2, t = lane & 3;
    const int wm = w & 3, wn = w >> 2;            // 4m x 2n; warp m64 x n32
    const int b = blockIdx.x;

    const float*  adjb = adj + (size_t)b * NP * NP;
    const __half* Sb   = S + (size_t)b * NP * HD;

    auto prefetch = [&](int c) {
        uint32_t st = sb + ((c & 1) ? AJ_ST1 : AJ_ST0);
        uint32_t bh = sb + ((c & 1) ? AJ_BH1 : AJ_BH0);
        #pragma unroll
        for (int i = 0; i < 4; i++) {             // adj: 1024 units
            int u = tid + i * 256;
            cpa16(st + u * 16, adjb + (size_t)(u >> 2) * NP + c * 16 + (u & 3) * 4);
        }
        if (tid < 128)                            // S chunk: 128 units
            cpa16(bh + (tid >> 3) * 144 + (tid & 7) * 16,
                  Sb + (size_t)(c * 16 + (tid >> 3)) * 64 + (tid & 7) * 8);
        asm volatile("cp.async.commit_group;\n");
    };

    // group 0: W + chunk 0
    #pragma unroll
    for (int i = 0; i < 2; i++) {
        int u = tid + i * 256;
        cpa16(sb + AJ_W + (u >> 3) * 144 + (u & 7) * 16, Wh + (u >> 3) * 64 + (u & 7) * 8);
    }
    #pragma unroll
    for (int i = 0; i < 4; i++) {
        int u = tid + i * 256;
        cpa16(sb + AJ_ST0 + u * 16, adjb + (size_t)(u >> 2) * NP + (u & 3) * 4);
    }
    if (tid < 128)
        cpa16(sb + AJ_BH0 + (tid >> 3) * 144 + (tid & 7) * 16,
              Sb + (size_t)(tid >> 3) * 64 + (tid & 7) * 8);
    asm volatile("cp.async.commit_group;\n");
    if (tid < HD) *reinterpret_cast<float*>(sm + AJ_BIAS + tid * 4) = bias[tid];

    float acc[4][4][4];
    #pragma unroll
    for (int i = 0; i < 4; i++)
        #pragma unroll
        for (int j = 0; j < 4; j++)
            #pragma unroll
            for (int r = 0; r < 4; r++) acc[i][j][r] = 0.f;

    for (int c = 0; c < 16; c++) {
        __syncthreads();                          // all warps past mma(c-1)
        if (c + 1 < 16) prefetch(c + 1);          // overwrites (c+1)&1 buffers
        if (c + 1 < 16) asm volatile("cp.async.wait_group 1;\n");  // chunk c in
        else            asm volatile("cp.async.wait_group 0;\n");
        __syncthreads();                          // chunk c visible CTA-wide

        // convert adj chunk fp32 -> half (Ah, 48B-pitch rows)
        uint32_t st = sb + ((c & 1) ? AJ_ST1 : AJ_ST0);
        uint32_t ah = sb + ((c & 1) ? AJ_AH1 : AJ_AH0);
        #pragma unroll
        for (int i = 0; i < 4; i++) {
            int u = tid + i * 256;
            int r = u >> 2, q = u & 3;
            float4 v = *reinterpret_cast<float4*>(sm + (st - sb) + u * 16);
            uint2 h;
            h.x = pk2h(v.x, v.y);
            h.y = pk2h(v.z, v.w);
            *reinterpret_cast<uint2*>(sm + (ah - sb) + r * 48 + q * 8) = h;
        }
        __syncthreads();                          // Ah visible

        uint32_t bh = sb + ((c & 1) ? AJ_BH1 : AJ_BH0);
        uint32_t a[4][4], bb[2][4];
        #pragma unroll
        for (int i = 0; i < 4; i++)
            ldsm4(a[i], ah + (wm * 64 + i * 16 + (lane & 15)) * 48 + (lane >> 4) * 16);
        #pragma unroll
        for (int p = 0; p < 2; p++)
            ldsm4t(bb[p], bh + (lane & 15) * 144
                          + (wn * 32 + p * 16 + (lane >> 4) * 8) * 2);
        #pragma unroll
        for (int j = 0; j < 4; j++) {
            uint32_t b0 = bb[j >> 1][(j & 1) * 2];
            uint32_t b1 = bb[j >> 1][(j & 1) * 2 + 1];
            #pragma unroll
            for (int i = 0; i < 4; i++) mma16(acc[i][j], a[i], b0, b1);
        }
    }

    __syncthreads();                              // stages/Ah dead -> T overlay

    // T = half(relu(acc/100)) at [row][col], 144B pitch
    #pragma unroll
    for (int i = 0; i < 4; i++)
        #pragma unroll
        for (int j = 0; j < 4; j++) {
            int r0 = wm * 64 + i * 16 + g;
            int col = wn * 32 + j * 8 + 2 * t;
            uint32_t h0 = pk2h(fmaxf(acc[i][j][0] * 0.01f, 0.f),
                               fmaxf(acc[i][j][1] * 0.01f, 0.f));
            uint32_t h1 = pk2h(fmaxf(acc[i][j][2] * 0.01f, 0.f),
                               fmaxf(acc[i][j][3] * 0.01f, 0.f));
            *reinterpret_cast<uint32_t*>(sm + AJ_T + r0 * 144 + col * 2)       = h0;
            *reinterpret_cast<uint32_t*>(sm + AJ_T + (r0 + 8) * 144 + col * 2) = h1;
        }
    __syncthreads();

    // U = T @ Wz
    #pragma unroll
    for (int i = 0; i < 4; i++)
        #pragma unroll
        for (int j = 0; j < 4; j++)
            #pragma unroll
            for (int r = 0; r < 4; r++) acc[i][j][r] = 0.f;

    #pragma unroll
    for (int ks = 0; ks < 4; ks++) {
        uint32_t a[4][4], bb[2][4];
        #pragma unroll
        for (int i = 0; i < 4; i++)
            ldsm4(a[i], sb + AJ_T + (wm * 64 + i * 16 + (lane & 15)) * 144
                        + ks * 32 + (lane >> 4) * 16);
        #pragma unroll
        for (int p = 0; p < 2; p++)
            ldsm4t(bb[p], sb + AJ_W + (ks * 16 + (lane & 15)) * 144
                          + (wn * 32 + p * 16 + (lane >> 4) * 8) * 2);
        #pragma unroll
        for (int j = 0; j < 4; j++) {
            uint32_t b0 = bb[j >> 1][(j & 1) * 2];
            uint32_t b1 = bb[j >> 1][(j & 1) * 2 + 1];
            #pragma unroll
            for (int i = 0; i < 4; i++) mma16(acc[i][j], a[i], b0, b1);
        }
    }

    const float* bsm = reinterpret_cast<const float*>(sm + AJ_BIAS);
    if (MASKED) {
        const float* mrow = nmask + (size_t)b * NP;
        #pragma unroll
        for (int i = 0; i < 4; i++) {
            int r0 = wm * 64 + i * 16 + g;
            float m0 = mrow[r0], m1 = mrow[r0 + 8];
            #pragma unroll
            for (int j = 0; j < 4; j++) {
                int col = wn * 32 + j * 8 + 2 * t;
                float b0 = bsm[col], b1 = bsm[col + 1];
                float2 v0, v1;
                v0.x = (acc[i][j][0] + b0) * m0;
                v0.y = (acc[i][j][1] + b1) * m0;
                v1.x = (acc[i][j][2] + b0) * m1;
                v1.y = (acc[i][j][3] + b1) * m1;
                *reinterpret_cast<float2*>(outf + ((size_t)b * NP + r0) * HD + col)     = v0;
                *reinterpret_cast<float2*>(outf + ((size_t)b * NP + r0 + 8) * HD + col) = v1;
            }
        }
    } else {
        #pragma unroll
        for (int i = 0; i < 4; i++) {
            int r0 = wm * 64 + i * 16 + g;
            #pragma unroll
            for (int j = 0; j < 4; j++) {
                int col = wn * 32 + j * 8 + 2 * t;
                float b0 = bsm[col], b1 = bsm[col + 1];
                uint32_t h0 = pk2h(acc[i][j][0] + b0, acc[i][j][1] + b1);
                uint32_t h1 = pk2h(acc[i][j][2] + b0, acc[i][j][3] + b1);
                *reinterpret_cast<uint32_t*>(outh + ((size_t)b * NP + r0) * HD + col)     = h0;
                *reinterpret_cast<uint32_t*>(outh + ((size_t)b * NP + r0 + 8) * HD + col) = h1;
            }
        }
    }
}

// ---------------------------------------------------------------------------
extern "C" void kernel_launch(void* const* d_in, const int* in_sizes, int n_in,
                              void* d_out, int out_size) {
    const float* x       = (const float*)d_in[0];
    const float* adj     = (const float*)d_in[1];
    const float* nmask   = (const float*)d_in[2];
    const float* W_embed = (const float*)d_in[3];
    const float* W0      = (const float*)d_in[4];
    const float* b0      = (const float*)d_in[5];
    const float* W1      = (const float*)d_in[6];
    const float* b1      = (const float*)d_in[7];
    const float* W_out   = (const float*)d_in[8];
    const float* b_out   = (const float*)d_in[9];
    float* out = (float*)d_out;

    __half *bufA = nullptr, *bufB = nullptr;
    uint16_t* wpre = nullptr;
    cudaGetSymbolAddress((void**)&bufA, g_bufA);
    cudaGetSymbolAddress((void**)&bufB, g_bufB);
    cudaGetSymbolAddress((void**)&wpre, g_WpreH);

    cudaFuncSetAttribute(kRowH, cudaFuncAttributeMaxDynamicSharedMemorySize, KR_BYTES);
    cudaFuncSetAttribute(kAdjH<0>, cudaFuncAttributeMaxDynamicSharedMemorySize, AJ_BYTES);
    cudaFuncSetAttribute(kAdjH<1>, cudaFuncAttributeMaxDynamicSharedMemorySize, AJ_BYTES);

    kPrep<<<48, 256>>>(W_embed, W0, W1, W_out, wpre);
    kRowH<<<1024, 256, KR_BYTES>>>(x, wpre, b0, bufA);
    kAdjH<0><<<512, 256, AJ_BYTES>>>(adj, bufA, wpre + 4096, b1, nullptr,
                                     nullptr, bufB);
    kAdjH<1><<<512, 256, AJ_BYTES>>>(adj, bufB, wpre + 8192, b_out, nmask,
                                     out, nullptr);
}

// round 10
// speedup vs baseline: 3.3613x; 1.1648x over previous
#include <cuda_runtime.h>
#include <cuda_fp16.h>
#include <cstdint>

// HGCN (math-reduced), fp16 mma.sync, register-pipelined:
//   kPrep : W01h=half(We@W0z); W1zh/Wozh=half(row0-zeroed W1/W_out)  [k][n]
//   kRowH : S0 = half(x @ W01 + b0)                  (row-major half)
//   kAdjC : S1 = half(relu(adj@S0/100) @ W1z + b1); also writes adj_h=half(adj)
//   kAdjF : out = (relu(adj_h@S1/100) @ Woz + b_out) * mask   (fp32)
// m16n8k16 HMMA fp32-accum; A via ldmatrix.x4 (64B swizzled rows), B/W/T via
// ldmatrix.x4.trans (144B pitch). One barrier per K-chunk.

static constexpr int NP = 256, HD = 64;

__device__ __half   g_bufA[131072 * 64];     // S0
__device__ __half   g_bufB[131072 * 64];     // S1
__device__ __half   g_adjh[512 * 256 * 256]; // half adj (written by kAdjC)
__device__ uint16_t g_WpreH[3 * 4096];

// ---- kAdjC smem (bytes) ----------------------------------------------------
static constexpr int C_ST = 0;        // fp32 adj stage 256x128B = 32768
static constexpr int C_A0 = 32768;    // half A tile 256x64B (swizzled)
static constexpr int C_A1 = 49152;
static constexpr int C_B0 = 65536;    // S chunk 32x144B = 4608
static constexpr int C_B1 = 70144;
static constexpr int C_W  = 74752;    // 64x144B = 9216
static constexpr int C_BYTES = 83968; // T tile (36864B) overlays offset 0
// ---- kAdjF smem ------------------------------------------------------------
static constexpr int F_A0 = 0;
static constexpr int F_A1 = 16384;
static constexpr int F_B0 = 32768;
static constexpr int F_B1 = 37376;
static constexpr int F_W  = 41984;
static constexpr int F_BYTES = 51200;
// ---- kRowH smem ------------------------------------------------------------
static constexpr int KR_ST   = 0;
static constexpr int KR_XH   = 32768;
static constexpr int KR_W    = 51200;
static constexpr int KR_BIAS = 60416;
static constexpr int KR_BYTES= 60672;

// ---- helpers ---------------------------------------------------------------
__device__ __forceinline__ uint32_t smem_u32(const void* p) {
    uint32_t a;
    asm("{ .reg .u64 t; cvta.to.shared.u64 t, %1; cvt.u32.u64 %0, t; }"
        : "=r"(a) : "l"(p));
    return a;
}
__device__ __forceinline__ void cpa16(uint32_t dst, const void* src) {
    asm volatile("cp.async.ca.shared.global [%0], [%1], 16;\n"
                 :: "r"(dst), "l"(src));
}
__device__ __forceinline__ void ldsm4(uint32_t* r, uint32_t addr) {
    asm volatile("ldmatrix.sync.aligned.m8n8.x4.shared.b16 {%0,%1,%2,%3}, [%4];"
                 : "=r"(r[0]), "=r"(r[1]), "=r"(r[2]), "=r"(r[3]) : "r"(addr));
}
__device__ __forceinline__ void ldsm4t(uint32_t* r, uint32_t addr) {
    asm volatile("ldmatrix.sync.aligned.m8n8.x4.trans.shared.b16 {%0,%1,%2,%3}, [%4];"
                 : "=r"(r[0]), "=r"(r[1]), "=r"(r[2]), "=r"(r[3]) : "r"(addr));
}
__device__ __forceinline__ void mma16(float* c, const uint32_t* a,
                                      uint32_t b0, uint32_t b1) {
    asm volatile(
        "mma.sync.aligned.m16n8k16.row.col.f32.f16.f16.f32 "
        "{%0,%1,%2,%3}, {%4,%5,%6,%7}, {%8,%9}, {%0,%1,%2,%3};\n"
        : "+f"(c[0]), "+f"(c[1]), "+f"(c[2]), "+f"(c[3])
        : "r"(a[0]), "r"(a[1]), "r"(a[2]), "r"(a[3]), "r"(b0), "r"(b1));
}
__device__ __forceinline__ uint32_t pk2h(float a, float b) {
    __half2 h = __floats2half2_rn(a, b);
    return *reinterpret_cast<uint32_t*>(&h);
}
// A-tile swizzle: 64B rows, 16B units; unit' = q ^ ((r>>1)&3)
__device__ __forceinline__ int aswz(int r, int q) {
    return r * 64 + ((q ^ ((r >> 1) & 3)) << 4);
}

// ---------------------------------------------------------------------------
__global__ void __launch_bounds__(256)
kPrep(const float* __restrict__ We, const float* __restrict__ W0,
      const float* __restrict__ W1, const float* __restrict__ Wo,
      uint16_t* __restrict__ WpreH) {
    int id = blockIdx.x * 256 + threadIdx.x;
    int which = id >> 12;
    int li = id & 4095;
    int k = li >> 6, n = li & 63;
    float v;
    if (which == 0) {
        float s = 0.f;
        #pragma unroll 8
        for (int kk = 1; kk < 64; kk++) s += We[k * 64 + kk] * W0[kk * 64 + n];
        v = s;
    } else {
        const float* W = (which == 1) ? W1 : Wo;
        v = (k == 0) ? 0.f : W[li];
    }
    __half h = __float2half_rn(v);
    WpreH[id] = *reinterpret_cast<uint16_t*>(&h);
}

// ---------------------------------------------------------------------------
// kRowH (unchanged from R9, passed): S0 = half(x @ W01 + b0)
// ---------------------------------------------------------------------------
__global__ void __launch_bounds__(256, 2)
kRowH(const float* __restrict__ X, const uint16_t* __restrict__ Wh,
      const float* __restrict__ bias, __half* __restrict__ S) {
    extern __shared__ char sm[];
    const uint32_t sb = smem_u32(sm);
    const int tid = threadIdx.x;
    const int lane = tid & 31, w = tid >> 5;
    const int g = lane >> 2, t = tid & 3;
    const int wm = w & 3, wn = w >> 2;
    const long row0 = (long)blockIdx.x * 128;

    #pragma unroll
    for (int i = 0; i < 8; i++) {
        int u = tid + i * 256;
        cpa16(sb + KR_ST + u * 16, X + (row0 + (u >> 4)) * 64 + (u & 15) * 4);
    }
    #pragma unroll
    for (int i = 0; i < 2; i++) {
        int u = tid + i * 256;
        cpa16(sb + KR_W + (u >> 3) * 144 + (u & 7) * 16,
              Wh + (u >> 3) * 64 + (u & 7) * 8);
    }
    asm volatile("cp.async.commit_group;\n");
    if (tid < HD) *reinterpret_cast<float*>(sm + KR_BIAS + tid * 4) = bias[tid];
    asm volatile("cp.async.wait_group 0;\n");
    __syncthreads();

    #pragma unroll
    for (int i = 0; i < 8; i++) {
        int u = tid + i * 256;
        int r = u >> 4, q = u & 15;
        float4 v = *reinterpret_cast<float4*>(sm + KR_ST + u * 16);
        uint2 h;
        h.x = pk2h(v.x, v.y);
        h.y = pk2h(v.z, v.w);
        *reinterpret_cast<uint2*>(sm + KR_XH + r * 144 + q * 8) = h;
    }
    __syncthreads();

    float acc[2][4][4];
    #pragma unroll
    for (int i = 0; i < 2; i++)
        #pragma unroll
        for (int j = 0; j < 4; j++)
            #pragma unroll
            for (int r = 0; r < 4; r++) acc[i][j][r] = 0.f;

    #pragma unroll
    for (int ks = 0; ks < 4; ks++) {
        uint32_t a[2][4], bb[2][4];
        #pragma unroll
        for (int i = 0; i < 2; i++)
            ldsm4(a[i], sb + KR_XH + (wm * 32 + i * 16 + (lane & 15)) * 144
                        + ks * 32 + (lane >> 4) * 16);
        #pragma unroll
        for (int p = 0; p < 2; p++)
            ldsm4t(bb[p], sb + KR_W + (ks * 16 + (lane & 15)) * 144
                          + (wn * 32 + p * 16 + (lane >> 4) * 8) * 2);
        #pragma unroll
        for (int j = 0; j < 4; j++) {
            uint32_t b0 = bb[j >> 1][(j & 1) * 2];
            uint32_t b1 = bb[j >> 1][(j & 1) * 2 + 1];
            mma16(acc[0][j], a[0], b0, b1);
            mma16(acc[1][j], a[1], b0, b1);
        }
    }

    const float* bsm = reinterpret_cast<const float*>(sm + KR_BIAS);
    #pragma unroll
    for (int i = 0; i < 2; i++)
        #pragma unroll
        for (int j = 0; j < 4; j++) {
            int col = wn * 32 + j * 8 + 2 * (lane & 3);
            float b0 = bsm[col], b1 = bsm[col + 1];
            int r0 = wm * 32 + i * 16 + g;
            uint32_t h0 = pk2h(acc[i][j][0] + b0, acc[i][j][1] + b1);
            uint32_t h1 = pk2h(acc[i][j][2] + b0, acc[i][j][3] + b1);
            *reinterpret_cast<uint32_t*>(S + (row0 + r0) * 64 + col)     = h0;
            *reinterpret_cast<uint32_t*>(S + (row0 + r0 + 8) * 64 + col) = h1;
        }
    (void)t;
}

// ---------------------------------------------------------------------------
// kAdjC: fp32 adj in; writes S1 (half) and adj_h (half). KT=32, 8 chunks.
// ---------------------------------------------------------------------------
__global__ void __launch_bounds__(256, 2)
kAdjC(const float* __restrict__ adj, const __half* __restrict__ S,
      const uint16_t* __restrict__ Wh, const float* __restrict__ bias,
      __half* __restrict__ S1, __half* __restrict__ adjh) {
    extern __shared__ char sm[];
    const uint32_t sb = smem_u32(sm);
    const int tid = threadIdx.x;
    const int lane = tid & 31, w = tid >> 5;
    const int g = lane >> 2, t = lane & 3;
    const int wm = w & 3, wn = w >> 2;
    const int b = blockIdx.x;

    const float*  adjb  = adj + (size_t)b * NP * NP;
    const __half* Sb    = S + (size_t)b * NP * HD;
    __half*       adjhb = adjh + (size_t)b * NP * NP;

    // prologue: cp.async A-fp32 chunk 0 + W (group 0); B chunk 0 via LDG
    #pragma unroll
    for (int i = 0; i < 8; i++) {
        int u = tid + i * 256;
        cpa16(sb + C_ST + u * 16, adjb + (size_t)(u >> 3) * NP + (u & 7) * 4);
    }
    #pragma unroll
    for (int i = 0; i < 2; i++) {
        int u = tid + i * 256;
        cpa16(sb + C_W + (u >> 3) * 144 + (u & 7) * 16,
              Wh + (u >> 3) * 64 + (u & 7) * 8);
    }
    asm volatile("cp.async.commit_group;\n");
    uint4 rB = *reinterpret_cast<const uint4*>(Sb + (size_t)(tid >> 3) * HD + (tid & 7) * 8);

    float acc[4][4][4];
    #pragma unroll
    for (int i = 0; i < 4; i++)
        #pragma unroll
        for (int j = 0; j < 4; j++)
            #pragma unroll
            for (int r = 0; r < 4; r++) acc[i][j][r] = 0.f;

    for (int c = 0; c < 8; c++) {
        asm volatile("cp.async.wait_group 0;\n");
        __syncthreads();                          // stage(c) visible everywhere

        const int AH = (c & 1) ? C_A1 : C_A0;
        const int BH = (c & 1) ? C_B1 : C_B0;
        // convert stage -> swizzled half tile + global adj_h
        #pragma unroll
        for (int i = 0; i < 8; i++) {
            int u = tid + i * 256;
            int r = u >> 3, q32 = u & 7;
            float4 v = *reinterpret_cast<float4*>(sm + C_ST + u * 16);
            uint2 h;
            h.x = pk2h(v.x, v.y);
            h.y = pk2h(v.z, v.w);
            *reinterpret_cast<uint2*>(sm + AH + aswz(r, q32 >> 1) + (q32 & 1) * 8) = h;
            *reinterpret_cast<uint2*>(adjhb + (size_t)r * NP + c * 32 + q32 * 4) = h;
        }
        // B chunk STS + reload next
        *reinterpret_cast<uint4*>(sm + BH + (tid >> 3) * 144 + (tid & 7) * 16) = rB;
        if (c + 1 < 8)
            rB = *reinterpret_cast<const uint4*>(
                Sb + (size_t)((c + 1) * 32 + (tid >> 3)) * HD + (tid & 7) * 8);
        __syncthreads();                          // halves visible; stage fully read

        if (c + 1 < 8) {                          // refill stage (overlaps mma)
            #pragma unroll
            for (int i = 0; i < 8; i++) {
                int u = tid + i * 256;
                cpa16(sb + C_ST + u * 16,
                      adjb + (size_t)(u >> 3) * NP + (c + 1) * 32 + (u & 7) * 4);
            }
            asm volatile("cp.async.commit_group;\n");
        }

        #pragma unroll
        for (int s = 0; s < 2; s++) {
            uint32_t a[4][4], bb[2][4];
            #pragma unroll
            for (int i = 0; i < 4; i++) {
                int r = wm * 64 + i * 16 + (lane & 15);
                ldsm4(a[i], sb + AH + aswz(r, 2 * s + (lane >> 4)));
            }
            #pragma unroll
            for (int p = 0; p < 2; p++)
                ldsm4t(bb[p], sb + BH + (s * 16 + (lane & 15)) * 144
                              + (wn * 32 + p * 16 + (lane >> 4) * 8) * 2);
            #pragma unroll
            for (int j = 0; j < 4; j++) {
                uint32_t b0 = bb[j >> 1][(j & 1) * 2];
                uint32_t b1 = bb[j >> 1][(j & 1) * 2 + 1];
                #pragma unroll
                for (int i = 0; i < 4; i++) mma16(acc[i][j], a[i], b0, b1);
            }
        }
    }

    __syncthreads();                              // everything dead -> T overlay

    #pragma unroll
    for (int i = 0; i < 4; i++)
        #pragma unroll
        for (int j = 0; j < 4; j++) {
            int r0 = wm * 64 + i * 16 + g;
            int col = wn * 32 + j * 8 + 2 * t;
            uint32_t h0 = pk2h(fmaxf(acc[i][j][0] * 0.01f, 0.f),
                               fmaxf(acc[i][j][1] * 0.01f, 0.f));
            uint32_t h1 = pk2h(fmaxf(acc[i][j][2] * 0.01f, 0.f),
                               fmaxf(acc[i][j][3] * 0.01f, 0.f));
            *reinterpret_cast<uint32_t*>(sm + r0 * 144 + col * 2)       = h0;
            *reinterpret_cast<uint32_t*>(sm + (r0 + 8) * 144 + col * 2) = h1;
        }
    __syncthreads();

    #pragma unroll
    for (int i = 0; i < 4; i++)
        #pragma unroll
        for (int j = 0; j < 4; j++)
            #pragma unroll
            for (int r = 0; r < 4; r++) acc[i][j][r] = 0.f;

    #pragma unroll
    for (int ks = 0; ks < 4; ks++) {
        uint32_t a[4][4], bb[2][4];
        #pragma unroll
        for (int i = 0; i < 4; i++)
            ldsm4(a[i], sb + (wm * 64 + i * 16 + (lane & 15)) * 144
                        + ks * 32 + (lane >> 4) * 16);
        #pragma unroll
        for (int p = 0; p < 2; p++)
            ldsm4t(bb[p], sb + C_W + (ks * 16 + (lane & 15)) * 144
                          + (wn * 32 + p * 16 + (lane >> 4) * 8) * 2);
        #pragma unroll
        for (int j = 0; j < 4; j++) {
            uint32_t b0 = bb[j >> 1][(j & 1) * 2];
            uint32_t b1 = bb[j >> 1][(j & 1) * 2 + 1];
            #pragma unroll
            for (int i = 0; i < 4; i++) mma16(acc[i][j], a[i], b0, b1);
        }
    }

    #pragma unroll
    for (int j = 0; j < 4; j++) {
        int col = wn * 32 + j * 8 + 2 * t;
        float b0 = bias[col], b1 = bias[col + 1];
        #pragma unroll
        for (int i = 0; i < 4; i++) {
            int r0 = wm * 64 + i * 16 + g;
            uint32_t h0 = pk2h(acc[i][j][0] + b0, acc[i][j][1] + b1);
            uint32_t h1 = pk2h(acc[i][j][2] + b0, acc[i][j][3] + b1);
            *reinterpret_cast<uint32_t*>(S1 + ((size_t)b * NP + r0) * HD + col)     = h0;
            *reinterpret_cast<uint32_t*>(S1 + ((size_t)b * NP + r0 + 8) * HD + col) = h1;
        }
    }
}

// ---------------------------------------------------------------------------
// kAdjF: half adj in; out = (relu(adj_h@S1/100) @ Woz + b_out) * mask. 8 chunks.
// ---------------------------------------------------------------------------
__global__ void __launch_bounds__(256, 2)
kAdjF(const __half* __restrict__ adjh, const __half* __restrict__ S,
      const uint16_t* __restrict__ Wh, const float* __restrict__ bias,
      const float* __restrict__ nmask, float* __restrict__ out) {
    extern __shared__ char sm[];
    const uint32_t sb = smem_u32(sm);
    const int tid = threadIdx.x;
    const int lane = tid & 31, w = tid >> 5;
    const int g = lane >> 2, t = lane & 3;
    const int wm = w & 3, wn = w >> 2;
    const int b = blockIdx.x;

    const __half* adjb = adjh + (size_t)b * NP * NP;
    const __half* Sb   = S + (size_t)b * NP * HD;

    // prologue: W via cp.async (waited in epilogue); chunk 0 via LDG
    #pragma unroll
    for (int i = 0; i < 2; i++) {
        int u = tid + i * 256;
        cpa16(sb + F_W + (u >> 3) * 144 + (u & 7) * 16,
              Wh + (u >> 3) * 64 + (u & 7) * 8);
    }
    asm volatile("cp.async.commit_group;\n");

    uint4 rA[4];
    #pragma unroll
    for (int i = 0; i < 4; i++) {
        int u = tid + i * 256;
        rA[i] = *reinterpret_cast<const uint4*>(
            adjb + (size_t)(u >> 2) * NP + (u & 3) * 8);
    }
    uint4 rB = *reinterpret_cast<const uint4*>(Sb + (size_t)(tid >> 3) * HD + (tid & 7) * 8);

    float acc[4][4][4];
    #pragma unroll
    for (int i = 0; i < 4; i++)
        #pragma unroll
        for (int j = 0; j < 4; j++)
            #pragma unroll
            for (int r = 0; r < 4; r++) acc[i][j][r] = 0.f;

    for (int c = 0; c < 8; c++) {
        const int AH = (c & 1) ? F_A1 : F_A0;
        const int BH = (c & 1) ? F_B1 : F_B0;
        #pragma unroll
        for (int i = 0; i < 4; i++) {
            int u = tid + i * 256;
            *reinterpret_cast<uint4*>(sm + AH + aswz(u >> 2, u & 3)) = rA[i];
        }
        *reinterpret_cast<uint4*>(sm + BH + (tid >> 3) * 144 + (tid & 7) * 16) = rB;
        if (c + 1 < 8) {
            #pragma unroll
            for (int i = 0; i < 4; i++) {
                int u = tid + i * 256;
                rA[i] = *reinterpret_cast<const uint4*>(
                    adjb + (size_t)(u >> 2) * NP + (c + 1) * 32 + (u & 3) * 8);
            }
            rB = *reinterpret_cast<const uint4*>(
                Sb + (size_t)((c + 1) * 32 + (tid >> 3)) * HD + (tid & 7) * 8);
        }
        __syncthreads();                          // single barrier per chunk

        #pragma unroll
        for (int s = 0; s < 2; s++) {
            uint32_t a[4][4], bb[2][4];
            #pragma unroll
            for (int i = 0; i < 4; i++) {
                int r = wm * 64 + i * 16 + (lane & 15);
                ldsm4(a[i], sb + AH + aswz(r, 2 * s + (lane >> 4)));
            }
            #pragma unroll
            for (int p = 0; p < 2; p++)
                ldsm4t(bb[p], sb + BH + (s * 16 + (lane & 15)) * 144
                              + (wn * 32 + p * 16 + (lane >> 4) * 8) * 2);
            #pragma unroll
            for (int j = 0; j < 4; j++) {
                uint32_t b0 = bb[j >> 1][(j & 1) * 2];
                uint32_t b1 = bb[j >> 1][(j & 1) * 2 + 1];
                #pragma unroll
                for (int i = 0; i < 4; i++) mma16(acc[i][j], a[i], b0, b1);
            }
        }
    }

    asm volatile("cp.async.wait_group 0;\n");     // W resident
    __syncthreads();                              // tiles dead -> T overlay

    #pragma unroll
    for (int i = 0; i < 4; i++)
        #pragma unroll
        for (int j = 0; j < 4; j++) {
            int r0 = wm * 64 + i * 16 + g;
            int col = wn * 32 + j * 8 + 2 * t;
            uint32_t h0 = pk2h(fmaxf(acc[i][j][0] * 0.01f, 0.f),
                               fmaxf(acc[i][j][1] * 0.01f, 0.f));
            uint32_t h1 = pk2h(fmaxf(acc[i][j][2] * 0.01f, 0.f),
                               fmaxf(acc[i][j][3] * 0.01f, 0.f));
            *reinterpret_cast<uint32_t*>(sm + r0 * 144 + col * 2)       = h0;
            *reinterpret_cast<uint32_t*>(sm + (r0 + 8) * 144 + col * 2) = h1;
        }
    __syncthreads();

    #pragma unroll
    for (int i = 0; i < 4; i++)
        #pragma unroll
        for (int j = 0; j < 4; j++)
            #pragma unroll
            for (int r = 0; r < 4; r++) acc[i][j][r] = 0.f;

    #pragma unroll
    for (int ks = 0; ks < 4; ks++) {
        uint32_t a[4][4], bb[2][4];
        #pragma unroll
        for (int i = 0; i < 4; i++)
            ldsm4(a[i], sb + (wm * 64 + i * 16 + (lane & 15)) * 144
                        + ks * 32 + (lane >> 4) * 16);
        #pragma unroll
        for (int p = 0; p < 2; p++)
            ldsm4t(bb[p], sb + F_W + (ks * 16 + (lane & 15)) * 144
                          + (wn * 32 + p * 16 + (lane >> 4) * 8) * 2);
        #pragma unroll
        for (int j = 0; j < 4; j++) {
            uint32_t b0 = bb[j >> 1][(j & 1) * 2];
            uint32_t b1 = bb[j >> 1][(j & 1) * 2 + 1];
            #pragma unroll
            for (int i = 0; i < 4; i++) mma16(acc[i][j], a[i], b0, b1);
        }
    }

    const float* mrow = nmask + (size_t)b * NP;
    #pragma unroll
    for (int j = 0; j < 4; j++) {
        int col = wn * 32 + j * 8 + 2 * t;
        float b0 = bias[col], b1 = bias[col + 1];
        #pragma unroll
        for (int i = 0; i < 4; i++) {
            int r0 = wm * 64 + i * 16 + g;
            float m0 = mrow[r0], m1 = mrow[r0 + 8];
            float2 v0, v1;
            v0.x = (acc[i][j][0] + b0) * m0;
            v0.y = (acc[i][j][1] + b1) * m0;
            v1.x = (acc[i][j][2] + b0) * m1;
            v1.y = (acc[i][j][3] + b1) * m1;
            *reinterpret_cast<float2*>(out + ((size_t)b * NP + r0) * HD + col)     = v0;
            *reinterpret_cast<float2*>(out + ((size_t)b * NP + r0 + 8) * HD + col) = v1;
        }
    }
}

// ---------------------------------------------------------------------------
extern "C" void kernel_launch(void* const* d_in, const int* in_sizes, int n_in,
                              void* d_out, int out_size) {
    const float* x       = (const float*)d_in[0];
    const float* adj     = (const float*)d_in[1];
    const float* nmask   = (const float*)d_in[2];
    const float* W_embed = (const float*)d_in[3];
    const float* W0      = (const float*)d_in[4];
    const float* b0      = (const float*)d_in[5];
    const float* W1      = (const float*)d_in[6];
    const float* b1      = (const float*)d_in[7];
    const float* W_out   = (const float*)d_in[8];
    const float* b_out   = (const float*)d_in[9];
    float* out = (float*)d_out;

    __half *bufA = nullptr, *bufB = nullptr, *adjh = nullptr;
    uint16_t* wpre = nullptr;
    cudaGetSymbolAddress((void**)&bufA, g_bufA);
    cudaGetSymbolAddress((void**)&bufB, g_bufB);
    cudaGetSymbolAddress((void**)&adjh, g_adjh);
    cudaGetSymbolAddress((void**)&wpre, g_WpreH);

    cudaFuncSetAttribute(kRowH, cudaFuncAttributeMaxDynamicSharedMemorySize, KR_BYTES);
    cudaFuncSetAttribute(kAdjC, cudaFuncAttributeMaxDynamicSharedMemorySize, C_BYTES);
    cudaFuncSetAttribute(kAdjF, cudaFuncAttributeMaxDynamicSharedMemorySize, F_BYTES);

    kPrep<<<48, 256>>>(W_embed, W0, W1, W_out, wpre);
    kRowH<<<1024, 256, KR_BYTES>>>(x, wpre, b0, bufA);
    kAdjC<<<512, 256, C_BYTES>>>(adj, bufA, wpre + 4096, b1, bufB, adjh);
    kAdjF<<<512, 256, F_BYTES>>>(adjh, bufB, wpre + 8192, b_out, nmask, out);
}